// round 4
// baseline (speedup 1.0000x reference)
#include <cuda_runtime.h>
#include <math.h>
#include <stdint.h>

#define BB 2
#define LL 4096
#define DD 512
#define HH 8
#define DKK 64
#define MROWS (BB*LL)          // 8192
#define QKVN (3*DD)            // 1536
#define ATTN_SCALE 0.125f      // 1/sqrt(64)

// Scratch (allocation-free rule: __device__ globals)
__device__ float g_qkv[(size_t)MROWS * QKVN];   // [B*L, 3*D]
__device__ float g_ctx[(size_t)MROWS * DD];     // [B*L, D]

// ---------------------------------------------------------------------------
// Helpers: tf32 convert + m16n8k8 tf32 MMA
// ---------------------------------------------------------------------------
__device__ __forceinline__ uint32_t f2tf(float x) {
    uint32_t u;
    asm("cvt.rna.tf32.f32 %0, %1;" : "=r"(u) : "f"(x));
    return u;
}

__device__ __forceinline__ uint4 f4tf(float4 v) {
    uint4 u;
    u.x = f2tf(v.x); u.y = f2tf(v.y); u.z = f2tf(v.z); u.w = f2tf(v.w);
    return u;
}

__device__ __forceinline__ void mma_tf32(float c[4],
    uint32_t a0, uint32_t a1, uint32_t a2, uint32_t a3,
    uint32_t b0, uint32_t b1)
{
    asm volatile(
        "mma.sync.aligned.m16n8k8.row.col.f32.tf32.tf32.f32 "
        "{%0,%1,%2,%3}, {%4,%5,%6,%7}, {%8,%9}, {%0,%1,%2,%3};"
        : "+f"(c[0]), "+f"(c[1]), "+f"(c[2]), "+f"(c[3])
        : "r"(a0), "r"(a1), "r"(a2), "r"(a3), "r"(b0), "r"(b1));
}

// ---------------------------------------------------------------------------
// tf32 GEMM: C[M,N] = A[M,K] @ W[N,K]^T  (row-major)
// Block tile 128x128, BK=32, 256 threads = 8 warps (4m x 2n),
// warp tile 32x64 (2 m16-frags x 8 n8-frags). Vectorized STS.128 staging.
// ---------------------------------------------------------------------------
#define GPAD 36   // 32 k + 4 pad

__global__ __launch_bounds__(256, 2) void gemm_tf32_kernel(
    const float* __restrict__ A, const float* __restrict__ W,
    float* __restrict__ C, int M, int N, int K)
{
    __shared__ uint32_t As[128 * GPAD];   // [m][k] tf32
    __shared__ uint32_t Ws[128 * GPAD];   // [n][k] tf32

    const int tid  = threadIdx.x;
    const int warp = tid >> 5;
    const int lane = tid & 31;
    const int g    = lane >> 2;
    const int tc   = lane & 3;
    const int wm   = (warp >> 1) * 32;
    const int wn   = (warp & 1) * 64;
    const int m0   = blockIdx.y * 128;
    const int n0   = blockIdx.x * 128;

    const int lrow = tid >> 1;            // 0..127
    const int lkof = (tid & 1) * 16;      // 0 / 16

    float acc[2][8][4];
#pragma unroll
    for (int mf = 0; mf < 2; mf++)
#pragma unroll
        for (int nf = 0; nf < 8; nf++)
#pragma unroll
            for (int i = 0; i < 4; i++) acc[mf][nf][i] = 0.0f;

    for (int k0 = 0; k0 < K; k0 += 32) {
        {
            const float* arow = &A[(size_t)(m0 + lrow) * K + k0 + lkof];
            const float* wrow = &W[(size_t)(n0 + lrow) * K + k0 + lkof];
#pragma unroll
            for (int j = 0; j < 16; j += 4) {
                float4 va = *reinterpret_cast<const float4*>(arow + j);
                *reinterpret_cast<uint4*>(&As[lrow * GPAD + lkof + j]) = f4tf(va);
                float4 vw = *reinterpret_cast<const float4*>(wrow + j);
                *reinterpret_cast<uint4*>(&Ws[lrow * GPAD + lkof + j]) = f4tf(vw);
            }
        }
        __syncthreads();

#pragma unroll
        for (int kk = 0; kk < 4; kk++) {
            const int kb = kk * 8;
            uint32_t a[2][4];
#pragma unroll
            for (int mf = 0; mf < 2; mf++) {
                const int rb = wm + mf * 16;
                a[mf][0] = As[(rb + g) * GPAD + kb + tc];
                a[mf][1] = As[(rb + g + 8) * GPAD + kb + tc];
                a[mf][2] = As[(rb + g) * GPAD + kb + tc + 4];
                a[mf][3] = As[(rb + g + 8) * GPAD + kb + tc + 4];
            }
#pragma unroll
            for (int nf = 0; nf < 8; nf++) {
                uint32_t b0 = Ws[(wn + nf * 8 + g) * GPAD + kb + tc];
                uint32_t b1 = Ws[(wn + nf * 8 + g) * GPAD + kb + tc + 4];
                mma_tf32(acc[0][nf], a[0][0], a[0][1], a[0][2], a[0][3], b0, b1);
                mma_tf32(acc[1][nf], a[1][0], a[1][1], a[1][2], a[1][3], b0, b1);
            }
        }
        __syncthreads();
    }

#pragma unroll
    for (int mf = 0; mf < 2; mf++) {
        const int r0 = m0 + wm + mf * 16 + g;
#pragma unroll
        for (int nf = 0; nf < 8; nf++) {
            const int cc = n0 + wn + nf * 8 + 2 * tc;
            *reinterpret_cast<float2*>(&C[(size_t)r0 * N + cc]) =
                make_float2(acc[mf][nf][0], acc[mf][nf][1]);
            *reinterpret_cast<float2*>(&C[(size_t)(r0 + 8) * N + cc]) =
                make_float2(acc[mf][nf][2], acc[mf][nf][3]);
        }
    }
}

// ---------------------------------------------------------------------------
// Flash attention, tf32 MMA, software-pipelined double-buffered K/V.
// 256 threads = 8 warps. Br=128 (16 rows/warp), Bc=64, DK=64.
// One __syncthreads per KV tile; K/V tile t+1 prefetched into registers
// during tile t's compute. P stays in registers (shuffle permutation).
// ---------------------------------------------------------------------------
#define BR 128
#define BC 64
#define NT (LL / BC)
#define KP 68
#define VP 72
#define KW (BC * KP)   // words per K stage
#define VW (BC * VP)   // words per V stage

#define SM_QS 0
#define SM_K0 (BR * KP)
#define SM_V0 (SM_K0 + 2 * KW)
#define ASM_WORDS (SM_V0 + 2 * VW)
#define ASM_BYTES (ASM_WORDS * 4)   // 106496 B

__global__ __launch_bounds__(256, 2) void attn_tf32_kernel(
    const float* __restrict__ qkv, float* __restrict__ ctx)
{
    extern __shared__ uint32_t sm[];
    uint32_t* Qs = sm + SM_QS;     // [BR][KP]

    const int tid  = threadIdx.x;
    const int warp = tid >> 5;
    const int lane = tid & 31;
    const int g    = lane >> 2;
    const int tc   = lane & 3;
    const int wm   = warp * 16;

    const int bh = blockIdx.y;
    const int b  = bh >> 3;
    const int h  = bh & 7;
    const int q0 = blockIdx.x * BR;

    const float* base = qkv + (size_t)b * LL * QKVN + h * DKK;

    // K/V loader mapping: 4 threads per row, 16 floats each.
    const int lr = tid >> 2;            // 0..63
    const int lc = (tid & 3) * 16;      // 0,16,32,48

    // ---- Prologue: load Q tile and K/V tile 0 ----
    {
        const int r  = tid >> 1;
        const int c0 = (tid & 1) * 32;
        const float* qrow = base + (size_t)(q0 + r) * QKVN;
#pragma unroll
        for (int j = 0; j < 32; j += 4) {
            float4 v = *reinterpret_cast<const float4*>(qrow + c0 + j);
            v.x *= ATTN_SCALE; v.y *= ATTN_SCALE; v.z *= ATTN_SCALE; v.w *= ATTN_SCALE;
            *reinterpret_cast<uint4*>(&Qs[r * KP + c0 + j]) = f4tf(v);
        }
        const float* krow = base + (size_t)lr * QKVN + DD;
        const float* vrow = krow + DD;
#pragma unroll
        for (int j = 0; j < 16; j += 4) {
            float4 vk = *reinterpret_cast<const float4*>(krow + lc + j);
            *reinterpret_cast<uint4*>(&sm[SM_K0 + lr * KP + lc + j]) = f4tf(vk);
            float4 vv = *reinterpret_cast<const float4*>(vrow + lc + j);
            *reinterpret_cast<uint4*>(&sm[SM_V0 + lr * VP + lc + j]) = f4tf(vv);
        }
    }
    __syncthreads();

    float oa[8][4];
#pragma unroll
    for (int n = 0; n < 8; n++)
#pragma unroll
        for (int i = 0; i < 4; i++) oa[n][i] = 0.0f;
    float m0 = -1e30f, m1 = -1e30f;
    float l0 = 0.0f,  l1 = 0.0f;

    const int srcA = g * 4 + (tc >> 1);
    const int srcB = srcA + 2;
    const bool odd = (tc & 1);

    for (int t = 0; t < NT; t++) {
        const int s = t & 1;
        const bool pf = (t + 1 < NT);
        const uint32_t* Kb = sm + SM_K0 + s * KW;
        const uint32_t* Vb = sm + SM_V0 + s * VW;
        uint32_t* Kn = sm + SM_K0 + (1 - s) * KW;
        uint32_t* Vn = sm + SM_V0 + (1 - s) * VW;
        const float* krow_n = base + (size_t)((t + 1) * BC + lr) * QKVN + DD;

        // Prefetch next K tile into registers (overlaps S-MMA).
        float4 kr[4];
        if (pf) {
#pragma unroll
            for (int j = 0; j < 4; j++)
                kr[j] = *reinterpret_cast<const float4*>(krow_n + lc + 4 * j);
        }

        // S = Q @ K^T : 16x64 per warp
        float sa[8][4];
#pragma unroll
        for (int n = 0; n < 8; n++)
#pragma unroll
            for (int i = 0; i < 4; i++) sa[n][i] = 0.0f;

#pragma unroll
        for (int k = 0; k < 64; k += 8) {
            uint32_t a0 = Qs[(wm + g) * KP + k + tc];
            uint32_t a1 = Qs[(wm + g + 8) * KP + k + tc];
            uint32_t a2 = Qs[(wm + g) * KP + k + tc + 4];
            uint32_t a3 = Qs[(wm + g + 8) * KP + k + tc + 4];
#pragma unroll
            for (int n = 0; n < 8; n++) {
                uint32_t b0 = Kb[(n * 8 + g) * KP + k + tc];
                uint32_t b1 = Kb[(n * 8 + g) * KP + k + tc + 4];
                mma_tf32(sa[n], a0, a1, a2, a3, b0, b1);
            }
        }

        // Store prefetched K to the other stage; start V prefetch.
        float4 vr[4];
        if (pf) {
#pragma unroll
            for (int j = 0; j < 4; j++)
                *reinterpret_cast<uint4*>(&Kn[lr * KP + lc + 4 * j]) = f4tf(kr[j]);
            const float* vrow_n = krow_n + DD;
#pragma unroll
            for (int j = 0; j < 4; j++)
                vr[j] = *reinterpret_cast<const float4*>(vrow_n + lc + 4 * j);
        }

        // Online softmax on fragments.
        float mx0 = -1e30f, mx1 = -1e30f;
#pragma unroll
        for (int n = 0; n < 8; n++) {
            mx0 = fmaxf(mx0, fmaxf(sa[n][0], sa[n][1]));
            mx1 = fmaxf(mx1, fmaxf(sa[n][2], sa[n][3]));
        }
        mx0 = fmaxf(mx0, __shfl_xor_sync(0xffffffffu, mx0, 1));
        mx0 = fmaxf(mx0, __shfl_xor_sync(0xffffffffu, mx0, 2));
        mx1 = fmaxf(mx1, __shfl_xor_sync(0xffffffffu, mx1, 1));
        mx1 = fmaxf(mx1, __shfl_xor_sync(0xffffffffu, mx1, 2));

        float mn0 = fmaxf(m0, mx0);
        float mn1 = fmaxf(m1, mx1);
        float alpha0 = __expf(m0 - mn0);
        float alpha1 = __expf(m1 - mn1);
        m0 = mn0; m1 = mn1;

        float sum0 = 0.0f, sum1 = 0.0f;
#pragma unroll
        for (int n = 0; n < 8; n++) {
            float p0 = __expf(sa[n][0] - m0);
            float p1 = __expf(sa[n][1] - m0);
            float p2 = __expf(sa[n][2] - m1);
            float p3 = __expf(sa[n][3] - m1);
            sum0 += p0 + p1;
            sum1 += p2 + p3;
            sa[n][0] = p0; sa[n][1] = p1; sa[n][2] = p2; sa[n][3] = p3;
        }
        l0 = l0 * alpha0 + sum0;
        l1 = l1 * alpha1 + sum1;

#pragma unroll
        for (int n = 0; n < 8; n++) {
            oa[n][0] *= alpha0; oa[n][1] *= alpha0;
            oa[n][2] *= alpha1; oa[n][3] *= alpha1;
        }

        // O += P @ V. P fragments from S fragments via shuffles.
#pragma unroll
        for (int kk = 0; kk < 8; kk++) {
            float v00 = __shfl_sync(0xffffffffu, sa[kk][0], srcA);
            float v01 = __shfl_sync(0xffffffffu, sa[kk][1], srcA);
            float v10 = __shfl_sync(0xffffffffu, sa[kk][2], srcA);
            float v11 = __shfl_sync(0xffffffffu, sa[kk][3], srcA);
            float w00 = __shfl_sync(0xffffffffu, sa[kk][0], srcB);
            float w01 = __shfl_sync(0xffffffffu, sa[kk][1], srcB);
            float w10 = __shfl_sync(0xffffffffu, sa[kk][2], srcB);
            float w11 = __shfl_sync(0xffffffffu, sa[kk][3], srcB);
            uint32_t pa0 = f2tf(odd ? v01 : v00);
            uint32_t pa1 = f2tf(odd ? v11 : v10);
            uint32_t pa2 = f2tf(odd ? w01 : w00);
            uint32_t pa3 = f2tf(odd ? w11 : w10);
            const int kb = kk * 8;
#pragma unroll
            for (int n = 0; n < 8; n++) {
                uint32_t b0 = Vb[(kb + tc) * VP + n * 8 + g];
                uint32_t b1 = Vb[(kb + tc + 4) * VP + n * 8 + g];
                mma_tf32(oa[n], pa0, pa1, pa2, pa3, b0, b1);
            }
        }

        // Store prefetched V; one sync ends the tile.
        if (pf) {
#pragma unroll
            for (int j = 0; j < 4; j++)
                *reinterpret_cast<uint4*>(&Vn[lr * VP + lc + 4 * j]) = f4tf(vr[j]);
            __syncthreads();
        }
    }

    // Finalize l across the quad, normalize, write ctx.
    l0 += __shfl_xor_sync(0xffffffffu, l0, 1);
    l0 += __shfl_xor_sync(0xffffffffu, l0, 2);
    l1 += __shfl_xor_sync(0xffffffffu, l1, 1);
    l1 += __shfl_xor_sync(0xffffffffu, l1, 2);
    float inv0 = 1.0f / l0;
    float inv1 = 1.0f / l1;

    const int r0 = q0 + wm + g;
    const int r1 = r0 + 8;
#pragma unroll
    for (int n = 0; n < 8; n++) {
        *reinterpret_cast<float2*>(
            &ctx[(size_t)(b * LL + r0) * DD + h * DKK + n * 8 + 2 * tc]) =
            make_float2(oa[n][0] * inv0, oa[n][1] * inv0);
        *reinterpret_cast<float2*>(
            &ctx[(size_t)(b * LL + r1) * DD + h * DKK + n * 8 + 2 * tc]) =
            make_float2(oa[n][2] * inv1, oa[n][3] * inv1);
    }
}

// ---------------------------------------------------------------------------
extern "C" void kernel_launch(void* const* d_in, const int* in_sizes, int n_in,
                              void* d_out, int out_size)
{
    const float* x     = (const float*)d_in[0];   // [B, L, D]
    const float* w_qkv = (const float*)d_in[1];   // [3D, D]
    const float* w_o   = (const float*)d_in[2];   // [D, D]
    float* out = (float*)d_out;                   // [B, L, D]

    float* qkv_p = nullptr;
    float* ctx_p = nullptr;
    cudaGetSymbolAddress((void**)&qkv_p, g_qkv);
    cudaGetSymbolAddress((void**)&ctx_p, g_ctx);
    cudaFuncSetAttribute(attn_tf32_kernel, cudaFuncAttributeMaxDynamicSharedMemorySize, ASM_BYTES);

    // 1) qkv = x @ w_qkv^T : [8192, 1536]
    {
        dim3 grid(QKVN / 128, MROWS / 128);
        gemm_tf32_kernel<<<grid, 256>>>(x, w_qkv, qkv_p, MROWS, QKVN, DD);
    }
    // 2) attention -> ctx
    {
        dim3 grid(LL / BR, BB * HH);
        attn_tf32_kernel<<<grid, 256, ASM_BYTES>>>(qkv_p, ctx_p);
    }
    // 3) out = ctx @ w_o^T : [8192, 512]
    {
        dim3 grid(DD / 128, MROWS / 128);
        gemm_tf32_kernel<<<grid, 256>>>(ctx_p, w_o, out, MROWS, DD, DD);
    }
}

// round 5
// speedup vs baseline: 1.3709x; 1.3709x over previous
#include <cuda_runtime.h>
#include <math.h>
#include <stdint.h>

#define BB 2
#define LL 4096
#define DD 512
#define HH 8
#define DKK 64
#define MROWS (BB*LL)          // 8192
#define QKVN (3*DD)            // 1536
// attention scale with log2(e) folded in: softmax done in base-2
#define QSCALE (0.125f * 1.4426950408889634f)

// Scratch (allocation-free rule: __device__ globals)
__device__ float g_qkv[(size_t)MROWS * QKVN];   // [B*L, 3*D]
__device__ float g_ctx[(size_t)MROWS * DD];     // [B*L, D]

// ---------------------------------------------------------------------------
// Helpers: tf32 convert + m16n8k8 tf32 MMA
// ---------------------------------------------------------------------------
__device__ __forceinline__ uint32_t f2tf(float x) {
    uint32_t u;
    asm("cvt.rna.tf32.f32 %0, %1;" : "=r"(u) : "f"(x));
    return u;
}

__device__ __forceinline__ void mma_tf32(float c[4],
    uint32_t a0, uint32_t a1, uint32_t a2, uint32_t a3,
    uint32_t b0, uint32_t b1)
{
    asm volatile(
        "mma.sync.aligned.m16n8k8.row.col.f32.tf32.tf32.f32 "
        "{%0,%1,%2,%3}, {%4,%5,%6,%7}, {%8,%9}, {%0,%1,%2,%3};"
        : "+f"(c[0]), "+f"(c[1]), "+f"(c[2]), "+f"(c[3])
        : "r"(a0), "r"(a1), "r"(a2), "r"(a3), "r"(b0), "r"(b1));
}

// ---------------------------------------------------------------------------
// tf32 GEMM (unchanged from the 868us-verified version):
// C[M,N] = A[M,K] @ W[N,K]^T, 128x128 tiles, BK=32, 8 warps (4m x 2n).
// ---------------------------------------------------------------------------
#define GPAD 36   // 32 k + 4 pad

__global__ __launch_bounds__(256, 2) void gemm_tf32_kernel(
    const float* __restrict__ A, const float* __restrict__ W,
    float* __restrict__ C, int M, int N, int K)
{
    __shared__ uint32_t As[128 * GPAD];   // [m][k] tf32
    __shared__ uint32_t Ws[128 * GPAD];   // [n][k] tf32

    const int tid  = threadIdx.x;
    const int warp = tid >> 5;
    const int lane = tid & 31;
    const int g    = lane >> 2;
    const int tc   = lane & 3;
    const int wm   = (warp >> 1) * 32;
    const int wn   = (warp & 1) * 64;
    const int m0   = blockIdx.y * 128;
    const int n0   = blockIdx.x * 128;

    const int lrow = tid >> 1;
    const int lkof = (tid & 1) * 16;

    float acc[2][8][4];
#pragma unroll
    for (int mf = 0; mf < 2; mf++)
#pragma unroll
        for (int nf = 0; nf < 8; nf++)
#pragma unroll
            for (int i = 0; i < 4; i++) acc[mf][nf][i] = 0.0f;

    for (int k0 = 0; k0 < K; k0 += 32) {
        {
            const float* arow = &A[(size_t)(m0 + lrow) * K + k0 + lkof];
            const float* wrow = &W[(size_t)(n0 + lrow) * K + k0 + lkof];
#pragma unroll
            for (int j = 0; j < 16; j += 4) {
                float4 va = *reinterpret_cast<const float4*>(arow + j);
                As[lrow * GPAD + lkof + j + 0] = f2tf(va.x);
                As[lrow * GPAD + lkof + j + 1] = f2tf(va.y);
                As[lrow * GPAD + lkof + j + 2] = f2tf(va.z);
                As[lrow * GPAD + lkof + j + 3] = f2tf(va.w);
                float4 vw = *reinterpret_cast<const float4*>(wrow + j);
                Ws[lrow * GPAD + lkof + j + 0] = f2tf(vw.x);
                Ws[lrow * GPAD + lkof + j + 1] = f2tf(vw.y);
                Ws[lrow * GPAD + lkof + j + 2] = f2tf(vw.z);
                Ws[lrow * GPAD + lkof + j + 3] = f2tf(vw.w);
            }
        }
        __syncthreads();

#pragma unroll
        for (int kk = 0; kk < 4; kk++) {
            const int kb = kk * 8;
            uint32_t a[2][4];
#pragma unroll
            for (int mf = 0; mf < 2; mf++) {
                const int rb = wm + mf * 16;
                a[mf][0] = As[(rb + g) * GPAD + kb + tc];
                a[mf][1] = As[(rb + g + 8) * GPAD + kb + tc];
                a[mf][2] = As[(rb + g) * GPAD + kb + tc + 4];
                a[mf][3] = As[(rb + g + 8) * GPAD + kb + tc + 4];
            }
#pragma unroll
            for (int nf = 0; nf < 8; nf++) {
                uint32_t b0 = Ws[(wn + nf * 8 + g) * GPAD + kb + tc];
                uint32_t b1 = Ws[(wn + nf * 8 + g) * GPAD + kb + tc + 4];
                mma_tf32(acc[0][nf], a[0][0], a[0][1], a[0][2], a[0][3], b0, b1);
                mma_tf32(acc[1][nf], a[1][0], a[1][1], a[1][2], a[1][3], b0, b1);
            }
        }
        __syncthreads();
    }

#pragma unroll
    for (int mf = 0; mf < 2; mf++) {
        const int r0 = m0 + wm + mf * 16 + g;
#pragma unroll
        for (int nf = 0; nf < 8; nf++) {
            const int cc = n0 + wn + nf * 8 + 2 * tc;
            *reinterpret_cast<float2*>(&C[(size_t)r0 * N + cc]) =
                make_float2(acc[mf][nf][0], acc[mf][nf][1]);
            *reinterpret_cast<float2*>(&C[(size_t)(r0 + 8) * N + cc]) =
                make_float2(acc[mf][nf][2], acc[mf][nf][3]);
        }
    }
}

// ---------------------------------------------------------------------------
// Flash attention, tf32 MMA, single-buffered (two syncs/tile, the verified-
// fast structure), with PAIR-PACKED smem layouts so every MMA fragment fetch
// is one conflict-free LDS.64:
//   Q/K: elem (r, k) at  r*72 + (k>>3)*8 + (k&3)*2 + ((k>>2)&1)
//        -> (kb+tc, kb+tc+4) adjacent
//   V:   elem (r, c) at  ((r>>3)*4 + (r&3))*136 + c*2 + ((r&7)>>2)
//        -> rows (kb+tc, kb+tc+4) of column c adjacent
// ---------------------------------------------------------------------------
#define BR 128
#define BC 64
#define QKP 72            // packed Q/K row stride (64 + 8 pad)
#define PVP 136           // packed V pair-row stride (128 + 8 pad)

#define SM_QS 0
#define SM_KS (BR * QKP)              // 9216
#define SM_VS (SM_KS + BC * QKP)      // + 4608
#define ASM_WORDS (SM_VS + 32 * PVP)  // + 4352 = 18176
#define ASM_BYTES (ASM_WORDS * 4)     // 72704 B -> 2 CTAs/SM

// packed Q/K word offset for element column k within a row
__device__ __forceinline__ int qk_off(int k) {
    return ((k >> 3) << 3) + ((k & 3) << 1) + ((k >> 2) & 1);
}

__global__ __launch_bounds__(256, 2) void attn_tf32_kernel(
    const float* __restrict__ qkv, float* __restrict__ ctx)
{
    extern __shared__ uint32_t sm[];
    uint32_t* Qs = sm + SM_QS;
    uint32_t* Ks = sm + SM_KS;
    uint32_t* Vp = sm + SM_VS;

    const int tid  = threadIdx.x;
    const int warp = tid >> 5;
    const int lane = tid & 31;
    const int g    = lane >> 2;
    const int tc   = lane & 3;
    const int wm   = warp * 16;

    const int bh = blockIdx.y;
    const int b  = bh >> 3;
    const int h  = bh & 7;
    const int q0 = blockIdx.x * BR;

    const float* base = qkv + (size_t)b * LL * QKVN + h * DKK;

    // Load Q tile (128x64), fold in QSCALE (incl. log2e), pack-convert.
    {
        const int r  = tid >> 1;
        const int c0 = (tid & 1) * 32;
        const float* qrow = base + (size_t)(q0 + r) * QKVN;
        uint32_t* qdst = &Qs[r * QKP];
#pragma unroll
        for (int j = 0; j < 32; j += 4) {
            float4 v = *reinterpret_cast<const float4*>(qrow + c0 + j);
            qdst[qk_off(c0 + j + 0)] = f2tf(v.x * QSCALE);
            qdst[qk_off(c0 + j + 1)] = f2tf(v.y * QSCALE);
            qdst[qk_off(c0 + j + 2)] = f2tf(v.z * QSCALE);
            qdst[qk_off(c0 + j + 3)] = f2tf(v.w * QSCALE);
        }
    }

    float oa[8][4];
#pragma unroll
    for (int n = 0; n < 8; n++)
#pragma unroll
        for (int i = 0; i < 4; i++) oa[n][i] = 0.0f;
    float m0 = -1e30f, m1 = -1e30f;
    float l0 = 0.0f,  l1 = 0.0f;

    const int srcA = g * 4 + (tc >> 1);
    const int srcB = srcA + 2;
    const bool odd = (tc & 1);

    // K/V loader mapping: 4 threads per row, 16 floats each.
    const int lr = tid >> 2;            // 0..63
    const int lc = (tid & 3) * 16;      // 0,16,32,48
    // V packed destination row pieces for this loader thread
    const int vpr   = ((lr >> 3) << 2) + (lr & 3);   // pair-row
    const int vhalf = (lr & 7) >> 2;                 // 0 or 1

    for (int kt = 0; kt < LL; kt += BC) {
        __syncthreads();   // prior tile's MMAs done; safe to overwrite K/V

        // Load K and V tiles (64x64 each), pack-convert to tf32.
        {
            const float* krow = base + (size_t)(kt + lr) * QKVN + DD;
            const float* vrow = krow + DD;
            uint32_t* kdst = &Ks[lr * QKP];
            uint32_t* vdst = &Vp[vpr * PVP + vhalf];
#pragma unroll
            for (int j = 0; j < 16; j += 4) {
                float4 vk = *reinterpret_cast<const float4*>(krow + lc + j);
                kdst[qk_off(lc + j + 0)] = f2tf(vk.x);
                kdst[qk_off(lc + j + 1)] = f2tf(vk.y);
                kdst[qk_off(lc + j + 2)] = f2tf(vk.z);
                kdst[qk_off(lc + j + 3)] = f2tf(vk.w);
                float4 vv = *reinterpret_cast<const float4*>(vrow + lc + j);
                vdst[(lc + j + 0) * 2] = f2tf(vv.x);
                vdst[(lc + j + 1) * 2] = f2tf(vv.y);
                vdst[(lc + j + 2) * 2] = f2tf(vv.z);
                vdst[(lc + j + 3) * 2] = f2tf(vv.w);
            }
        }
        __syncthreads();

        // S = Q @ K^T : 16x64 per warp, all fragment fetches LDS.64
        float sa[8][4];
#pragma unroll
        for (int n = 0; n < 8; n++)
#pragma unroll
            for (int i = 0; i < 4; i++) sa[n][i] = 0.0f;

#pragma unroll
        for (int kk = 0; kk < 8; kk++) {
            const int kb = kk * 8;
            uint2 qa = *reinterpret_cast<const uint2*>(&Qs[(wm + g) * QKP + kb + tc * 2]);      // a0,a2
            uint2 qb = *reinterpret_cast<const uint2*>(&Qs[(wm + g + 8) * QKP + kb + tc * 2]);  // a1,a3
#pragma unroll
            for (int n = 0; n < 8; n++) {
                uint2 kb2 = *reinterpret_cast<const uint2*>(&Ks[(n * 8 + g) * QKP + kb + tc * 2]);
                mma_tf32(sa[n], qa.x, qb.x, qa.y, qb.y, kb2.x, kb2.y);
            }
        }

        // Online softmax (base-2) on fragments.
        float mx0 = -1e30f, mx1 = -1e30f;
#pragma unroll
        for (int n = 0; n < 8; n++) {
            mx0 = fmaxf(mx0, fmaxf(sa[n][0], sa[n][1]));
            mx1 = fmaxf(mx1, fmaxf(sa[n][2], sa[n][3]));
        }
        mx0 = fmaxf(mx0, __shfl_xor_sync(0xffffffffu, mx0, 1));
        mx0 = fmaxf(mx0, __shfl_xor_sync(0xffffffffu, mx0, 2));
        mx1 = fmaxf(mx1, __shfl_xor_sync(0xffffffffu, mx1, 1));
        mx1 = fmaxf(mx1, __shfl_xor_sync(0xffffffffu, mx1, 2));

        float mn0 = fmaxf(m0, mx0);
        float mn1 = fmaxf(m1, mx1);
        float alpha0 = exp2f(m0 - mn0);
        float alpha1 = exp2f(m1 - mn1);
        m0 = mn0; m1 = mn1;

        float sum0 = 0.0f, sum1 = 0.0f;
#pragma unroll
        for (int n = 0; n < 8; n++) {
            float p0 = exp2f(sa[n][0] - m0);
            float p1 = exp2f(sa[n][1] - m0);
            float p2 = exp2f(sa[n][2] - m1);
            float p3 = exp2f(sa[n][3] - m1);
            sum0 += p0 + p1;
            sum1 += p2 + p3;
            sa[n][0] = p0; sa[n][1] = p1; sa[n][2] = p2; sa[n][3] = p3;
        }
        l0 = l0 * alpha0 + sum0;
        l1 = l1 * alpha1 + sum1;

#pragma unroll
        for (int n = 0; n < 8; n++) {
            oa[n][0] *= alpha0; oa[n][1] *= alpha0;
            oa[n][2] *= alpha1; oa[n][3] *= alpha1;
        }

        // O += P @ V. P fragments via shuffles; V fragment fetches LDS.64.
#pragma unroll
        for (int kk = 0; kk < 8; kk++) {
            float v00 = __shfl_sync(0xffffffffu, sa[kk][0], srcA);
            float v01 = __shfl_sync(0xffffffffu, sa[kk][1], srcA);
            float v10 = __shfl_sync(0xffffffffu, sa[kk][2], srcA);
            float v11 = __shfl_sync(0xffffffffu, sa[kk][3], srcA);
            float w00 = __shfl_sync(0xffffffffu, sa[kk][0], srcB);
            float w01 = __shfl_sync(0xffffffffu, sa[kk][1], srcB);
            float w10 = __shfl_sync(0xffffffffu, sa[kk][2], srcB);
            float w11 = __shfl_sync(0xffffffffu, sa[kk][3], srcB);
            uint32_t pa0 = f2tf(odd ? v01 : v00);
            uint32_t pa1 = f2tf(odd ? v11 : v10);
            uint32_t pa2 = f2tf(odd ? w01 : w00);
            uint32_t pa3 = f2tf(odd ? w11 : w10);
            const uint32_t* vrowp = &Vp[(kk * 4 + tc) * PVP + g * 2];
#pragma unroll
            for (int n = 0; n < 8; n++) {
                uint2 vv = *reinterpret_cast<const uint2*>(vrowp + n * 16);
                mma_tf32(oa[n], pa0, pa1, pa2, pa3, vv.x, vv.y);
            }
        }
    }

    // Finalize l across the quad, normalize, write ctx.
    l0 += __shfl_xor_sync(0xffffffffu, l0, 1);
    l0 += __shfl_xor_sync(0xffffffffu, l0, 2);
    l1 += __shfl_xor_sync(0xffffffffu, l1, 1);
    l1 += __shfl_xor_sync(0xffffffffu, l1, 2);
    float inv0 = 1.0f / l0;
    float inv1 = 1.0f / l1;

    const int r0 = q0 + wm + g;
    const int r1 = r0 + 8;
#pragma unroll
    for (int n = 0; n < 8; n++) {
        *reinterpret_cast<float2*>(
            &ctx[(size_t)(b * LL + r0) * DD + h * DKK + n * 8 + 2 * tc]) =
            make_float2(oa[n][0] * inv0, oa[n][1] * inv0);
        *reinterpret_cast<float2*>(
            &ctx[(size_t)(b * LL + r1) * DD + h * DKK + n * 8 + 2 * tc]) =
            make_float2(oa[n][2] * inv1, oa[n][3] * inv1);
    }
}

// ---------------------------------------------------------------------------
extern "C" void kernel_launch(void* const* d_in, const int* in_sizes, int n_in,
                              void* d_out, int out_size)
{
    const float* x     = (const float*)d_in[0];   // [B, L, D]
    const float* w_qkv = (const float*)d_in[1];   // [3D, D]
    const float* w_o   = (const float*)d_in[2];   // [D, D]
    float* out = (float*)d_out;                   // [B, L, D]

    float* qkv_p = nullptr;
    float* ctx_p = nullptr;
    cudaGetSymbolAddress((void**)&qkv_p, g_qkv);
    cudaGetSymbolAddress((void**)&ctx_p, g_ctx);
    cudaFuncSetAttribute(attn_tf32_kernel, cudaFuncAttributeMaxDynamicSharedMemorySize, ASM_BYTES);

    // 1) qkv = x @ w_qkv^T : [8192, 1536]
    {
        dim3 grid(QKVN / 128, MROWS / 128);
        gemm_tf32_kernel<<<grid, 256>>>(x, w_qkv, qkv_p, MROWS, QKVN, DD);
    }
    // 2) attention -> ctx
    {
        dim3 grid(LL / BR, BB * HH);
        attn_tf32_kernel<<<grid, 256, ASM_BYTES>>>(qkv_p, ctx_p);
    }
    // 3) out = ctx @ w_o^T : [8192, 512]
    {
        dim3 grid(DD / 128, MROWS / 128);
        gemm_tf32_kernel<<<grid, 256>>>(ctx_p, w_o, out, MROWS, DD, DD);
    }
}

// round 6
// speedup vs baseline: 1.5502x; 1.1308x over previous
#include <cuda_runtime.h>
#include <math.h>
#include <stdint.h>

#define BB 2
#define LL 4096
#define DD 512
#define HH 8
#define DKK 64
#define MROWS (BB*LL)          // 8192
#define QKVN (3*DD)            // 1536
// attention scale with log2(e) folded in: softmax in base-2
#define QSCALE (0.125f * 1.4426950408889634f)

// Scratch (allocation-free rule: __device__ globals)
__device__ float g_qkv[(size_t)MROWS * QKVN];   // [B*L, 3*D]
__device__ float g_ctx[(size_t)MROWS * DD];     // [B*L, D]

// ---------------------------------------------------------------------------
// Helpers
// ---------------------------------------------------------------------------
__device__ __forceinline__ uint32_t f2tf(float x) {
    uint32_t u;
    asm("cvt.rna.tf32.f32 %0, %1;" : "=r"(u) : "f"(x));
    return u;
}

__device__ __forceinline__ void mma_tf32(float c[4],
    uint32_t a0, uint32_t a1, uint32_t a2, uint32_t a3,
    uint32_t b0, uint32_t b1)
{
    asm volatile(
        "mma.sync.aligned.m16n8k8.row.col.f32.tf32.tf32.f32 "
        "{%0,%1,%2,%3}, {%4,%5,%6,%7}, {%8,%9}, {%0,%1,%2,%3};"
        : "+f"(c[0]), "+f"(c[1]), "+f"(c[2]), "+f"(c[3])
        : "r"(a0), "r"(a1), "r"(a2), "r"(a3), "r"(b0), "r"(b1));
}

__device__ __forceinline__ void cp16(float* smem_dst, const float* gmem_src) {
    uint32_t sa = (uint32_t)__cvta_generic_to_shared(smem_dst);
    asm volatile("cp.async.cg.shared.global [%0], [%1], 16;" :: "r"(sa), "l"(gmem_src));
}

// ---------------------------------------------------------------------------
// tf32 GEMM, cp.async double-buffered: C[M,N] = A[M,K] @ W[N,K]^T.
// 128x128 tiles, BK=32, 8 warps (4m x 2n), warp tile 32x64.
// Raw fp32 staged in smem; cvt.rna applied at fragment load (numerics
// identical to cvt-at-store). One __syncthreads per k-iter.
// ---------------------------------------------------------------------------
#define GPAD 36                 // 32 k + 4 pad (144B row stride, 16B aligned)
#define GSTG (128 * GPAD)       // words per array per stage
#define GSM_BYTES (2 * 2 * GSTG * 4)   // 73728 B

__global__ __launch_bounds__(256, 2) void gemm_tf32_kernel(
    const float* __restrict__ A, const float* __restrict__ W,
    float* __restrict__ C, int M, int N, int K)
{
    extern __shared__ float gsm[];   // [stage][As | Ws]

    const int tid  = threadIdx.x;
    const int warp = tid >> 5;
    const int lane = tid & 31;
    const int g    = lane >> 2;
    const int tc   = lane & 3;
    const int wm   = (warp >> 1) * 32;
    const int wn   = (warp & 1) * 64;
    const int m0   = blockIdx.y * 128;
    const int n0   = blockIdx.x * 128;

    const int lrow = tid >> 1;        // 0..127
    const int lkof = (tid & 1) * 16;  // 0 / 16

    float acc[2][8][4];
#pragma unroll
    for (int mf = 0; mf < 2; mf++)
#pragma unroll
        for (int nf = 0; nf < 8; nf++)
#pragma unroll
            for (int i = 0; i < 4; i++) acc[mf][nf][i] = 0.0f;

    const int NK = K >> 5;   // 32-wide k iters

    // Prologue: issue stage 0
    {
        const float* arow = &A[(size_t)(m0 + lrow) * K + lkof];
        const float* wrow = &W[(size_t)(n0 + lrow) * K + lkof];
        float* as = gsm;
        float* ws = gsm + GSTG;
#pragma unroll
        for (int j = 0; j < 4; j++) {
            cp16(&as[lrow * GPAD + lkof + j * 4], arow + j * 4);
            cp16(&ws[lrow * GPAD + lkof + j * 4], wrow + j * 4);
        }
        asm volatile("cp.async.commit_group;");
    }

    for (int i = 0; i < NK; i++) {
        asm volatile("cp.async.wait_group 0;");
        __syncthreads();   // stage i ready; all warps done with stage i-1

        if (i + 1 < NK) {
            const int st = (i + 1) & 1;
            const int k0 = (i + 1) << 5;
            const float* arow = &A[(size_t)(m0 + lrow) * K + k0 + lkof];
            const float* wrow = &W[(size_t)(n0 + lrow) * K + k0 + lkof];
            float* as = gsm + st * 2 * GSTG;
            float* ws = as + GSTG;
#pragma unroll
            for (int j = 0; j < 4; j++) {
                cp16(&as[lrow * GPAD + lkof + j * 4], arow + j * 4);
                cp16(&ws[lrow * GPAD + lkof + j * 4], wrow + j * 4);
            }
            asm volatile("cp.async.commit_group;");
        }

        const float* as = gsm + (i & 1) * 2 * GSTG;
        const float* ws = as + GSTG;
#pragma unroll
        for (int kk = 0; kk < 4; kk++) {
            const int kb = kk * 8;
            uint32_t a[2][4];
#pragma unroll
            for (int mf = 0; mf < 2; mf++) {
                const int rb = wm + mf * 16;
                a[mf][0] = f2tf(as[(rb + g) * GPAD + kb + tc]);
                a[mf][1] = f2tf(as[(rb + g + 8) * GPAD + kb + tc]);
                a[mf][2] = f2tf(as[(rb + g) * GPAD + kb + tc + 4]);
                a[mf][3] = f2tf(as[(rb + g + 8) * GPAD + kb + tc + 4]);
            }
#pragma unroll
            for (int nf = 0; nf < 8; nf++) {
                uint32_t b0 = f2tf(ws[(wn + nf * 8 + g) * GPAD + kb + tc]);
                uint32_t b1 = f2tf(ws[(wn + nf * 8 + g) * GPAD + kb + tc + 4]);
                mma_tf32(acc[0][nf], a[0][0], a[0][1], a[0][2], a[0][3], b0, b1);
                mma_tf32(acc[1][nf], a[1][0], a[1][1], a[1][2], a[1][3], b0, b1);
            }
        }
    }

#pragma unroll
    for (int mf = 0; mf < 2; mf++) {
        const int r0 = m0 + wm + mf * 16 + g;
#pragma unroll
        for (int nf = 0; nf < 8; nf++) {
            const int cc = n0 + wn + nf * 8 + 2 * tc;
            *reinterpret_cast<float2*>(&C[(size_t)r0 * N + cc]) =
                make_float2(acc[mf][nf][0], acc[mf][nf][1]);
            *reinterpret_cast<float2*>(&C[(size_t)(r0 + 8) * N + cc]) =
                make_float2(acc[mf][nf][2], acc[mf][nf][3]);
        }
    }
}

// ---------------------------------------------------------------------------
// Flash attention, tf32 MMA — EXACT 868us-verified structure (KP=68/VP=72,
// scalar cvt-at-store, two syncs/tile, shuffle-P), plus two layout-free cuts:
//   * base-2 softmax (log2e folded into Q scale; exp2f)
//   * warp-uniform skip of the O-rescale when the running max didn't change
// ---------------------------------------------------------------------------
#define BR 128
#define BC 64
#define KP 68
#define VP 72

#define SM_QS 0
#define SM_KS (BR*KP)
#define SM_VS (SM_KS + BC*KP)
#define ASM_WORDS (SM_VS + BC*VP)
#define ASM_BYTES (ASM_WORDS * 4)

__global__ __launch_bounds__(256, 2) void attn_tf32_kernel(
    const float* __restrict__ qkv, float* __restrict__ ctx)
{
    extern __shared__ uint32_t sm[];
    uint32_t* Qs = sm + SM_QS;   // [BR][KP]
    uint32_t* Ks = sm + SM_KS;   // [BC][KP]
    uint32_t* Vs = sm + SM_VS;   // [BC][VP]

    const int tid  = threadIdx.x;
    const int warp = tid >> 5;
    const int lane = tid & 31;
    const int g    = lane >> 2;
    const int tc   = lane & 3;
    const int wm   = warp * 16;

    const int bh = blockIdx.y;
    const int b  = bh >> 3;
    const int h  = bh & 7;
    const int q0 = blockIdx.x * BR;

    const float* base = qkv + (size_t)b * LL * QKVN + h * DKK;

    // Load Q tile (128x64), fold in QSCALE (incl. log2e), convert to tf32.
    {
        const int r  = tid >> 1;
        const int c0 = (tid & 1) * 32;
        const float* qrow = base + (size_t)(q0 + r) * QKVN;
#pragma unroll
        for (int j = 0; j < 32; j += 4) {
            float4 v = *reinterpret_cast<const float4*>(qrow + c0 + j);
            Qs[r * KP + c0 + j + 0] = f2tf(v.x * QSCALE);
            Qs[r * KP + c0 + j + 1] = f2tf(v.y * QSCALE);
            Qs[r * KP + c0 + j + 2] = f2tf(v.z * QSCALE);
            Qs[r * KP + c0 + j + 3] = f2tf(v.w * QSCALE);
        }
    }

    float oa[8][4];
#pragma unroll
    for (int n = 0; n < 8; n++)
#pragma unroll
        for (int i = 0; i < 4; i++) oa[n][i] = 0.0f;
    float m0 = -1e30f, m1 = -1e30f;
    float l0 = 0.0f,  l1 = 0.0f;

    const int srcA = g * 4 + (tc >> 1);
    const int srcB = srcA + 2;
    const bool odd = (tc & 1);

    for (int kt = 0; kt < LL; kt += BC) {
        __syncthreads();   // prior PV done; safe to overwrite Ks/Vs

        // Load K and V tiles (64x64 each), convert to tf32.
        {
            const int r  = tid >> 2;
            const int c0 = (tid & 3) * 16;
            const float* krow = base + (size_t)(kt + r) * QKVN + DD;
            const float* vrow = krow + DD;
#pragma unroll
            for (int j = 0; j < 16; j += 4) {
                float4 vk = *reinterpret_cast<const float4*>(krow + c0 + j);
                Ks[r * KP + c0 + j + 0] = f2tf(vk.x);
                Ks[r * KP + c0 + j + 1] = f2tf(vk.y);
                Ks[r * KP + c0 + j + 2] = f2tf(vk.z);
                Ks[r * KP + c0 + j + 3] = f2tf(vk.w);
                float4 vv = *reinterpret_cast<const float4*>(vrow + c0 + j);
                Vs[r * VP + c0 + j + 0] = f2tf(vv.x);
                Vs[r * VP + c0 + j + 1] = f2tf(vv.y);
                Vs[r * VP + c0 + j + 2] = f2tf(vv.z);
                Vs[r * VP + c0 + j + 3] = f2tf(vv.w);
            }
        }
        __syncthreads();

        // S = Q @ K^T : 16x64 per warp
        float sa[8][4];
#pragma unroll
        for (int n = 0; n < 8; n++)
#pragma unroll
            for (int i = 0; i < 4; i++) sa[n][i] = 0.0f;

#pragma unroll
        for (int k = 0; k < 64; k += 8) {
            uint32_t a0 = Qs[(wm + g) * KP + k + tc];
            uint32_t a1 = Qs[(wm + g + 8) * KP + k + tc];
            uint32_t a2 = Qs[(wm + g) * KP + k + tc + 4];
            uint32_t a3 = Qs[(wm + g + 8) * KP + k + tc + 4];
#pragma unroll
            for (int n = 0; n < 8; n++) {
                uint32_t b0 = Ks[(n * 8 + g) * KP + k + tc];
                uint32_t b1 = Ks[(n * 8 + g) * KP + k + tc + 4];
                mma_tf32(sa[n], a0, a1, a2, a3, b0, b1);
            }
        }

        // Online softmax (base-2) on fragments.
        float mx0 = -1e30f, mx1 = -1e30f;
#pragma unroll
        for (int n = 0; n < 8; n++) {
            mx0 = fmaxf(mx0, fmaxf(sa[n][0], sa[n][1]));
            mx1 = fmaxf(mx1, fmaxf(sa[n][2], sa[n][3]));
        }
        mx0 = fmaxf(mx0, __shfl_xor_sync(0xffffffffu, mx0, 1));
        mx0 = fmaxf(mx0, __shfl_xor_sync(0xffffffffu, mx0, 2));
        mx1 = fmaxf(mx1, __shfl_xor_sync(0xffffffffu, mx1, 1));
        mx1 = fmaxf(mx1, __shfl_xor_sync(0xffffffffu, mx1, 2));

        // Warp-uniform: does any row's max move this tile?
        const bool upd = !__all_sync(0xffffffffu, (mx0 <= m0) & (mx1 <= m1));
        if (upd) {
            float mn0 = fmaxf(m0, mx0);
            float mn1 = fmaxf(m1, mx1);
            float alpha0 = exp2f(m0 - mn0);
            float alpha1 = exp2f(m1 - mn1);
            m0 = mn0; m1 = mn1;
            l0 *= alpha0;
            l1 *= alpha1;
#pragma unroll
            for (int n = 0; n < 8; n++) {
                oa[n][0] *= alpha0; oa[n][1] *= alpha0;
                oa[n][2] *= alpha1; oa[n][3] *= alpha1;
            }
        }

        float sum0 = 0.0f, sum1 = 0.0f;
#pragma unroll
        for (int n = 0; n < 8; n++) {
            float p0 = exp2f(sa[n][0] - m0);
            float p1 = exp2f(sa[n][1] - m0);
            float p2 = exp2f(sa[n][2] - m1);
            float p3 = exp2f(sa[n][3] - m1);
            sum0 += p0 + p1;
            sum1 += p2 + p3;
            sa[n][0] = p0; sa[n][1] = p1; sa[n][2] = p2; sa[n][3] = p3;
        }
        l0 += sum0;
        l1 += sum1;

        // O += P @ V. P fragments from S fragments via shuffles.
#pragma unroll
        for (int kk = 0; kk < 8; kk++) {
            float v00 = __shfl_sync(0xffffffffu, sa[kk][0], srcA);
            float v01 = __shfl_sync(0xffffffffu, sa[kk][1], srcA);
            float v10 = __shfl_sync(0xffffffffu, sa[kk][2], srcA);
            float v11 = __shfl_sync(0xffffffffu, sa[kk][3], srcA);
            float w00 = __shfl_sync(0xffffffffu, sa[kk][0], srcB);
            float w01 = __shfl_sync(0xffffffffu, sa[kk][1], srcB);
            float w10 = __shfl_sync(0xffffffffu, sa[kk][2], srcB);
            float w11 = __shfl_sync(0xffffffffu, sa[kk][3], srcB);
            uint32_t pa0 = f2tf(odd ? v01 : v00);
            uint32_t pa1 = f2tf(odd ? v11 : v10);
            uint32_t pa2 = f2tf(odd ? w01 : w00);
            uint32_t pa3 = f2tf(odd ? w11 : w10);
            const int kb = kk * 8;
#pragma unroll
            for (int n = 0; n < 8; n++) {
                uint32_t b0 = Vs[(kb + tc) * VP + n * 8 + g];
                uint32_t b1 = Vs[(kb + tc + 4) * VP + n * 8 + g];
                mma_tf32(oa[n], pa0, pa1, pa2, pa3, b0, b1);
            }
        }
    }

    // Finalize l across the quad, normalize, write ctx.
    l0 += __shfl_xor_sync(0xffffffffu, l0, 1);
    l0 += __shfl_xor_sync(0xffffffffu, l0, 2);
    l1 += __shfl_xor_sync(0xffffffffu, l1, 1);
    l1 += __shfl_xor_sync(0xffffffffu, l1, 2);
    float inv0 = 1.0f / l0;
    float inv1 = 1.0f / l1;

    const int r0 = q0 + wm + g;
    const int r1 = r0 + 8;
#pragma unroll
    for (int n = 0; n < 8; n++) {
        *reinterpret_cast<float2*>(
            &ctx[(size_t)(b * LL + r0) * DD + h * DKK + n * 8 + 2 * tc]) =
            make_float2(oa[n][0] * inv0, oa[n][1] * inv0);
        *reinterpret_cast<float2*>(
            &ctx[(size_t)(b * LL + r1) * DD + h * DKK + n * 8 + 2 * tc]) =
            make_float2(oa[n][2] * inv1, oa[n][3] * inv1);
    }
}

// ---------------------------------------------------------------------------
extern "C" void kernel_launch(void* const* d_in, const int* in_sizes, int n_in,
                              void* d_out, int out_size)
{
    const float* x     = (const float*)d_in[0];   // [B, L, D]
    const float* w_qkv = (const float*)d_in[1];   // [3D, D]
    const float* w_o   = (const float*)d_in[2];   // [D, D]
    float* out = (float*)d_out;                   // [B, L, D]

    float* qkv_p = nullptr;
    float* ctx_p = nullptr;
    cudaGetSymbolAddress((void**)&qkv_p, g_qkv);
    cudaGetSymbolAddress((void**)&ctx_p, g_ctx);
    cudaFuncSetAttribute(gemm_tf32_kernel, cudaFuncAttributeMaxDynamicSharedMemorySize, GSM_BYTES);
    cudaFuncSetAttribute(attn_tf32_kernel, cudaFuncAttributeMaxDynamicSharedMemorySize, ASM_BYTES);

    // 1) qkv = x @ w_qkv^T : [8192, 1536]
    {
        dim3 grid(QKVN / 128, MROWS / 128);
        gemm_tf32_kernel<<<grid, 256, GSM_BYTES>>>(x, w_qkv, qkv_p, MROWS, QKVN, DD);
    }
    // 2) attention -> ctx
    {
        dim3 grid(LL / BR, BB * HH);
        attn_tf32_kernel<<<grid, 256, ASM_BYTES>>>(qkv_p, ctx_p);
    }
    // 3) out = ctx @ w_o^T : [8192, 512]
    {
        dim3 grid(DD / 128, MROWS / 128);
        gemm_tf32_kernel<<<grid, 256, GSM_BYTES>>>(ctx_p, w_o, out, MROWS, DD, DD);
    }
}

// round 8
// speedup vs baseline: 1.6095x; 1.0383x over previous
#include <cuda_runtime.h>
#include <math.h>
#include <stdint.h>

#define BB 2
#define LL 4096
#define DD 512
#define HH 8
#define DKK 64
#define MROWS (BB*LL)          // 8192
#define QKVN (3*DD)            // 1536
// softmax scale (1/sqrt(64) * log2(e)); applied inside exp2, not to Q
#define CC (0.125f * 1.4426950408889634f)

// Scratch (allocation-free rule: __device__ globals)
__device__ float g_qkv[(size_t)MROWS * QKVN];   // [B*L, 3*D] (tf32-exact values)
__device__ float g_ctx[(size_t)MROWS * DD];     // [B*L, D]

// ---------------------------------------------------------------------------
// Helpers
// ---------------------------------------------------------------------------
__device__ __forceinline__ uint32_t f2tf(float x) {
    uint32_t u;
    asm("cvt.rna.tf32.f32 %0, %1;" : "=r"(u) : "f"(x));
    return u;
}

__device__ __forceinline__ void mma_tf32(float c[4],
    uint32_t a0, uint32_t a1, uint32_t a2, uint32_t a3,
    uint32_t b0, uint32_t b1)
{
    asm volatile(
        "mma.sync.aligned.m16n8k8.row.col.f32.tf32.tf32.f32 "
        "{%0,%1,%2,%3}, {%4,%5,%6,%7}, {%8,%9}, {%0,%1,%2,%3};"
        : "+f"(c[0]), "+f"(c[1]), "+f"(c[2]), "+f"(c[3])
        : "r"(a0), "r"(a1), "r"(a2), "r"(a3), "r"(b0), "r"(b1));
}

__device__ __forceinline__ uint32_t smem_u32(const void* p) {
    uint32_t a;
    asm("{ .reg .u64 t; cvta.to.shared.u64 t, %1; cvt.u32.u64 %0, t; }"
        : "=r"(a) : "l"(p));
    return a;
}

__device__ __forceinline__ void cp16s(uint32_t smem_addr, const float* gptr) {
    asm volatile("cp.async.cg.shared.global [%0], [%1], 16;"
                 :: "r"(smem_addr), "l"(gptr));
}

// ---------------------------------------------------------------------------
// tf32 GEMM (142us-verified structure): C[M,N] = A[M,K] @ W[N,K]^T.
// 128x128 tiles, BK=32, 8 warps (4m x 2n), warp tile 32x64.
// round_out != 0 -> outputs are rounded to tf32-exact fp32 (for qkv buffer).
// ---------------------------------------------------------------------------
#define GPAD 36   // 32 k + 4 pad

__global__ __launch_bounds__(256, 2) void gemm_tf32_kernel(
    const float* __restrict__ A, const float* __restrict__ W,
    float* __restrict__ C, int M, int N, int K, int round_out)
{
    __shared__ uint32_t As[128 * GPAD];   // [m][k] tf32
    __shared__ uint32_t Ws[128 * GPAD];   // [n][k] tf32

    const int tid  = threadIdx.x;
    const int warp = tid >> 5;
    const int lane = tid & 31;
    const int g    = lane >> 2;
    const int tc   = lane & 3;
    const int wm   = (warp >> 1) * 32;
    const int wn   = (warp & 1) * 64;
    const int m0   = blockIdx.y * 128;
    const int n0   = blockIdx.x * 128;

    const int lrow = tid >> 1;
    const int lkof = (tid & 1) * 16;

    float acc[2][8][4];
#pragma unroll
    for (int mf = 0; mf < 2; mf++)
#pragma unroll
        for (int nf = 0; nf < 8; nf++)
#pragma unroll
            for (int i = 0; i < 4; i++) acc[mf][nf][i] = 0.0f;

    for (int k0 = 0; k0 < K; k0 += 32) {
        {
            const float* arow = &A[(size_t)(m0 + lrow) * K + k0 + lkof];
            const float* wrow = &W[(size_t)(n0 + lrow) * K + k0 + lkof];
#pragma unroll
            for (int j = 0; j < 16; j += 4) {
                float4 va = *reinterpret_cast<const float4*>(arow + j);
                As[lrow * GPAD + lkof + j + 0] = f2tf(va.x);
                As[lrow * GPAD + lkof + j + 1] = f2tf(va.y);
                As[lrow * GPAD + lkof + j + 2] = f2tf(va.z);
                As[lrow * GPAD + lkof + j + 3] = f2tf(va.w);
                float4 vw = *reinterpret_cast<const float4*>(wrow + j);
                Ws[lrow * GPAD + lkof + j + 0] = f2tf(vw.x);
                Ws[lrow * GPAD + lkof + j + 1] = f2tf(vw.y);
                Ws[lrow * GPAD + lkof + j + 2] = f2tf(vw.z);
                Ws[lrow * GPAD + lkof + j + 3] = f2tf(vw.w);
            }
        }
        __syncthreads();

#pragma unroll
        for (int kk = 0; kk < 4; kk++) {
            const int kb = kk * 8;
            uint32_t a[2][4];
#pragma unroll
            for (int mf = 0; mf < 2; mf++) {
                const int rb = wm + mf * 16;
                a[mf][0] = As[(rb + g) * GPAD + kb + tc];
                a[mf][1] = As[(rb + g + 8) * GPAD + kb + tc];
                a[mf][2] = As[(rb + g) * GPAD + kb + tc + 4];
                a[mf][3] = As[(rb + g + 8) * GPAD + kb + tc + 4];
            }
#pragma unroll
            for (int nf = 0; nf < 8; nf++) {
                uint32_t b0 = Ws[(wn + nf * 8 + g) * GPAD + kb + tc];
                uint32_t b1 = Ws[(wn + nf * 8 + g) * GPAD + kb + tc + 4];
                mma_tf32(acc[0][nf], a[0][0], a[0][1], a[0][2], a[0][3], b0, b1);
                mma_tf32(acc[1][nf], a[1][0], a[1][1], a[1][2], a[1][3], b0, b1);
            }
        }
        __syncthreads();
    }

#pragma unroll
    for (int mf = 0; mf < 2; mf++) {
        const int r0 = m0 + wm + mf * 16 + g;
#pragma unroll
        for (int nf = 0; nf < 8; nf++) {
            const int cc = n0 + wn + nf * 8 + 2 * tc;
            float o0 = acc[mf][nf][0], o1 = acc[mf][nf][1];
            float o2 = acc[mf][nf][2], o3 = acc[mf][nf][3];
            if (round_out) {
                o0 = __uint_as_float(f2tf(o0));
                o1 = __uint_as_float(f2tf(o1));
                o2 = __uint_as_float(f2tf(o2));
                o3 = __uint_as_float(f2tf(o3));
            }
            *reinterpret_cast<float2*>(&C[(size_t)r0 * N + cc]) = make_float2(o0, o1);
            *reinterpret_cast<float2*>(&C[(size_t)(r0 + 8) * N + cc]) = make_float2(o2, o3);
        }
    }
}

// ---------------------------------------------------------------------------
// Flash attention, tf32 mma.sync. qkv buffer holds tf32-exact fp32 values, so
// K/V/Q stage via bare cp.async (no cvt, no register round-trip), K/V double-
// buffered: one commit + one wait + one __syncthreads per tile. The softmax
// scale is folded into the exp2 argument (subtract becomes FMA).
// ---------------------------------------------------------------------------
#define BR 128
#define BC 64
#define NT (LL / BC)
#define KP 68
#define VP 72
#define QW (BR * KP)    // 8704
#define KW (BC * KP)    // 4352
#define VW (BC * VP)    // 4608
#define ASM_WORDS (QW + 2 * KW + 2 * VW)   // 26624
#define ASM_BYTES (ASM_WORDS * 4)          // 106496 -> 2 CTAs/SM

__global__ __launch_bounds__(256, 2) void attn_tf32_kernel(
    const float* __restrict__ qkv, float* __restrict__ ctx)
{
    extern __shared__ uint32_t sm[];
    uint32_t* Qs = sm;                      // [BR][KP]
    const uint32_t sb = smem_u32(sm);

    const int tid  = threadIdx.x;
    const int warp = tid >> 5;
    const int lane = tid & 31;
    const int g    = lane >> 2;
    const int tc   = lane & 3;
    const int wm   = warp * 16;

    const int bh = blockIdx.y;
    const int b  = bh >> 3;
    const int h  = bh & 7;
    const int q0 = blockIdx.x * BR;

    const float* base = qkv + (size_t)b * LL * QKVN + h * DKK;

    // loader mapping for K/V tiles: 4 threads/row, 16 floats each
    const int lr = tid >> 2;            // 0..63
    const int lc = (tid & 3) * 16;      // 0,16,32,48

    // ---- Prologue: cp.async Q tile + K/V tile 0, one group ----
    {
        const int r  = tid >> 1;
        const int c0 = (tid & 1) * 32;
        const float* qrow = base + (size_t)(q0 + r) * QKVN;
#pragma unroll
        for (int j = 0; j < 8; j++)
            cp16s(sb + 4 * (r * KP + c0 + 4 * j), qrow + c0 + 4 * j);

        const float* krow = base + (size_t)lr * QKVN + DD;
        const float* vrow = krow + DD;
#pragma unroll
        for (int j = 0; j < 4; j++) {
            cp16s(sb + 4 * (QW + lr * KP + lc + 4 * j), krow + lc + 4 * j);
            cp16s(sb + 4 * (QW + 2 * KW + lr * VP + lc + 4 * j), vrow + lc + 4 * j);
        }
        asm volatile("cp.async.commit_group;");
        asm volatile("cp.async.wait_group 0;");
    }
    __syncthreads();

    float oa[8][4];
#pragma unroll
    for (int n = 0; n < 8; n++)
#pragma unroll
        for (int i = 0; i < 4; i++) oa[n][i] = 0.0f;
    float m0 = -1e30f, m1 = -1e30f;   // running max, RAW (unscaled) domain
    float l0 = 0.0f,  l1 = 0.0f;

    const int srcA = g * 4 + (tc >> 1);
    const int srcB = srcA + 2;
    const bool odd = (tc & 1);

    for (int t = 0; t < NT; t++) {
        const bool pf = (t + 1 < NT);
        const uint32_t* Ks = sm + QW + (t & 1) * KW;
        const uint32_t* Vs = sm + QW + 2 * KW + (t & 1) * VW;

        // Issue next tile's K/V into the alternate stage (async, no regs).
        if (pf) {
            const float* krow = base + (size_t)((t + 1) * BC + lr) * QKVN + DD;
            const float* vrow = krow + DD;
            const uint32_t kd = sb + 4 * (QW + ((t + 1) & 1) * KW);
            const uint32_t vd = sb + 4 * (QW + 2 * KW + ((t + 1) & 1) * VW);
#pragma unroll
            for (int j = 0; j < 4; j++) {
                cp16s(kd + 4 * (lr * KP + lc + 4 * j), krow + lc + 4 * j);
                cp16s(vd + 4 * (lr * VP + lc + 4 * j), vrow + lc + 4 * j);
            }
            asm volatile("cp.async.commit_group;");
        }

        // S = Q @ K^T : 16x64 per warp (raw, unscaled)
        float sa[8][4];
#pragma unroll
        for (int n = 0; n < 8; n++)
#pragma unroll
            for (int i = 0; i < 4; i++) sa[n][i] = 0.0f;

#pragma unroll
        for (int k = 0; k < 64; k += 8) {
            uint32_t a0 = Qs[(wm + g) * KP + k + tc];
            uint32_t a1 = Qs[(wm + g + 8) * KP + k + tc];
            uint32_t a2 = Qs[(wm + g) * KP + k + tc + 4];
            uint32_t a3 = Qs[(wm + g + 8) * KP + k + tc + 4];
#pragma unroll
            for (int n = 0; n < 8; n++) {
                uint32_t b0 = Ks[(n * 8 + g) * KP + k + tc];
                uint32_t b1 = Ks[(n * 8 + g) * KP + k + tc + 4];
                mma_tf32(sa[n], a0, a1, a2, a3, b0, b1);
            }
        }

        // Online softmax; scale CC folded into exp2 argument.
        float mx0 = -1e30f, mx1 = -1e30f;
#pragma unroll
        for (int n = 0; n < 8; n++) {
            mx0 = fmaxf(mx0, fmaxf(sa[n][0], sa[n][1]));
            mx1 = fmaxf(mx1, fmaxf(sa[n][2], sa[n][3]));
        }
        mx0 = fmaxf(mx0, __shfl_xor_sync(0xffffffffu, mx0, 1));
        mx0 = fmaxf(mx0, __shfl_xor_sync(0xffffffffu, mx0, 2));
        mx1 = fmaxf(mx1, __shfl_xor_sync(0xffffffffu, mx1, 1));
        mx1 = fmaxf(mx1, __shfl_xor_sync(0xffffffffu, mx1, 2));

        const bool upd = !__all_sync(0xffffffffu, (mx0 <= m0) & (mx1 <= m1));
        if (upd) {
            float mn0 = fmaxf(m0, mx0);
            float mn1 = fmaxf(m1, mx1);
            float alpha0 = exp2f(CC * (m0 - mn0));
            float alpha1 = exp2f(CC * (m1 - mn1));
            m0 = mn0; m1 = mn1;
            l0 *= alpha0;
            l1 *= alpha1;
#pragma unroll
            for (int n = 0; n < 8; n++) {
                oa[n][0] *= alpha0; oa[n][1] *= alpha0;
                oa[n][2] *= alpha1; oa[n][3] *= alpha1;
            }
        }

        const float nc0 = -CC * m0;
        const float nc1 = -CC * m1;
        float sum0 = 0.0f, sum1 = 0.0f;
#pragma unroll
        for (int n = 0; n < 8; n++) {
            float p0 = exp2f(fmaf(CC, sa[n][0], nc0));
            float p1 = exp2f(fmaf(CC, sa[n][1], nc0));
            float p2 = exp2f(fmaf(CC, sa[n][2], nc1));
            float p3 = exp2f(fmaf(CC, sa[n][3], nc1));
            sum0 += p0 + p1;
            sum1 += p2 + p3;
            sa[n][0] = p0; sa[n][1] = p1; sa[n][2] = p2; sa[n][3] = p3;
        }
        l0 += sum0;
        l1 += sum1;

        // O += P @ V. P fragments from S fragments via shuffles.
#pragma unroll
        for (int kk = 0; kk < 8; kk++) {
            float v00 = __shfl_sync(0xffffffffu, sa[kk][0], srcA);
            float v01 = __shfl_sync(0xffffffffu, sa[kk][1], srcA);
            float v10 = __shfl_sync(0xffffffffu, sa[kk][2], srcA);
            float v11 = __shfl_sync(0xffffffffu, sa[kk][3], srcA);
            float w00 = __shfl_sync(0xffffffffu, sa[kk][0], srcB);
            float w01 = __shfl_sync(0xffffffffu, sa[kk][1], srcB);
            float w10 = __shfl_sync(0xffffffffu, sa[kk][2], srcB);
            float w11 = __shfl_sync(0xffffffffu, sa[kk][3], srcB);
            uint32_t pa0 = f2tf(odd ? v01 : v00);
            uint32_t pa1 = f2tf(odd ? v11 : v10);
            uint32_t pa2 = f2tf(odd ? w01 : w00);
            uint32_t pa3 = f2tf(odd ? w11 : w10);
            const int kb = kk * 8;
#pragma unroll
            for (int n = 0; n < 8; n++) {
                uint32_t b0 = Vs[(kb + tc) * VP + n * 8 + g];
                uint32_t b1 = Vs[(kb + tc + 4) * VP + n * 8 + g];
                mma_tf32(oa[n], pa0, pa1, pa2, pa3, b0, b1);
            }
        }

        if (pf) { asm volatile("cp.async.wait_group 0;"); }
        __syncthreads();
    }

    // Finalize l across the quad, normalize, write ctx.
    l0 += __shfl_xor_sync(0xffffffffu, l0, 1);
    l0 += __shfl_xor_sync(0xffffffffu, l0, 2);
    l1 += __shfl_xor_sync(0xffffffffu, l1, 1);
    l1 += __shfl_xor_sync(0xffffffffu, l1, 2);
    float inv0 = 1.0f / l0;
    float inv1 = 1.0f / l1;

    const int r0 = q0 + wm + g;
    const int r1 = r0 + 8;
#pragma unroll
    for (int n = 0; n < 8; n++) {
        *reinterpret_cast<float2*>(
            &ctx[(size_t)(b * LL + r0) * DD + h * DKK + n * 8 + 2 * tc]) =
            make_float2(oa[n][0] * inv0, oa[n][1] * inv0);
        *reinterpret_cast<float2*>(
            &ctx[(size_t)(b * LL + r1) * DD + h * DKK + n * 8 + 2 * tc]) =
            make_float2(oa[n][2] * inv1, oa[n][3] * inv1);
    }
}

// ---------------------------------------------------------------------------
extern "C" void kernel_launch(void* const* d_in, const int* in_sizes, int n_in,
                              void* d_out, int out_size)
{
    const float* x     = (const float*)d_in[0];   // [B, L, D]
    const float* w_qkv = (const float*)d_in[1];   // [3D, D]
    const float* w_o   = (const float*)d_in[2];   // [D, D]
    float* out = (float*)d_out;                   // [B, L, D]

    float* qkv_p = nullptr;
    float* ctx_p = nullptr;
    cudaGetSymbolAddress((void**)&qkv_p, g_qkv);
    cudaGetSymbolAddress((void**)&ctx_p, g_ctx);
    cudaFuncSetAttribute(attn_tf32_kernel, cudaFuncAttributeMaxDynamicSharedMemorySize, ASM_BYTES);

    // 1) qkv = x @ w_qkv^T : [8192, 1536], outputs rounded to tf32-exact
    {
        dim3 grid(QKVN / 128, MROWS / 128);
        gemm_tf32_kernel<<<grid, 256>>>(x, w_qkv, qkv_p, MROWS, QKVN, DD, 1);
    }
    // 2) attention -> ctx
    {
        dim3 grid(LL / BR, BB * HH);
        attn_tf32_kernel<<<grid, 256, ASM_BYTES>>>(qkv_p, ctx_p);
    }
    // 3) out = ctx @ w_o^T : [8192, 512], plain fp32 output
    {
        dim3 grid(DD / 128, MROWS / 128);
        gemm_tf32_kernel<<<grid, 256>>>(ctx_p, w_o, out, MROWS, DD, DD, 0);
    }
}

// round 9
// speedup vs baseline: 1.7505x; 1.0876x over previous
#include <cuda_runtime.h>
#include <math.h>
#include <stdint.h>

#define BB 2
#define LL 4096
#define DD 512
#define HH 8
#define DKK 64
#define MROWS (BB*LL)          // 8192
#define QKVN (3*DD)            // 1536
// softmax scale (1/sqrt(64) * log2(e)); applied inside exp2
#define CC (0.125f * 1.4426950408889634f)

// Scratch (allocation-free rule: __device__ globals)
__device__ float g_qkv[(size_t)MROWS * QKVN];   // [B*L, 3*D] (tf32-exact values)
__device__ float g_ctx[(size_t)MROWS * DD];     // [B*L, D]

// ---------------------------------------------------------------------------
// Helpers
// ---------------------------------------------------------------------------
__device__ __forceinline__ uint32_t f2tf(float x) {
    uint32_t u;
    asm("cvt.rna.tf32.f32 %0, %1;" : "=r"(u) : "f"(x));
    return u;
}

__device__ __forceinline__ float ex2(float x) {
    float y;
    asm("ex2.approx.ftz.f32 %0, %1;" : "=f"(y) : "f"(x));
    return y;
}

__device__ __forceinline__ void mma_tf32(float c[4],
    uint32_t a0, uint32_t a1, uint32_t a2, uint32_t a3,
    uint32_t b0, uint32_t b1)
{
    asm volatile(
        "mma.sync.aligned.m16n8k8.row.col.f32.tf32.tf32.f32 "
        "{%0,%1,%2,%3}, {%4,%5,%6,%7}, {%8,%9}, {%0,%1,%2,%3};"
        : "+f"(c[0]), "+f"(c[1]), "+f"(c[2]), "+f"(c[3])
        : "r"(a0), "r"(a1), "r"(a2), "r"(a3), "r"(b0), "r"(b1));
}

// ldmatrix x4: four 8x8 16B-row matrices; per-lane addr in shared space.
__device__ __forceinline__ void ldsm4(uint32_t& r0, uint32_t& r1,
                                      uint32_t& r2, uint32_t& r3, uint32_t addr)
{
    asm volatile("ldmatrix.sync.aligned.m8n8.x4.shared.b16 {%0,%1,%2,%3}, [%4];"
                 : "=r"(r0), "=r"(r1), "=r"(r2), "=r"(r3) : "r"(addr));
}

__device__ __forceinline__ uint32_t smem_u32(const void* p) {
    uint32_t a;
    asm("{ .reg .u64 t; cvta.to.shared.u64 t, %1; cvt.u32.u64 %0, t; }"
        : "=r"(a) : "l"(p));
    return a;
}

__device__ __forceinline__ void cp16s(uint32_t smem_addr, const float* gptr) {
    asm volatile("cp.async.cg.shared.global [%0], [%1], 16;"
                 :: "r"(smem_addr), "l"(gptr));
}

// ---------------------------------------------------------------------------
// tf32 GEMM: C[M,N] = A[M,K] @ W[N,K]^T. 128x128 tiles, BK=32, 8 warps
// (4m x 2n), warp tile 32x64. Fragment loads via ldmatrix.x4.
// round_out != 0 -> outputs rounded to tf32-exact fp32 (for qkv buffer).
// ---------------------------------------------------------------------------
#define GPAD 36   // 32 k + 4 pad (144B rows, 16B aligned)

__global__ __launch_bounds__(256, 2) void gemm_tf32_kernel(
    const float* __restrict__ A, const float* __restrict__ W,
    float* __restrict__ C, int M, int N, int K, int round_out)
{
    __shared__ uint32_t As[128 * GPAD];   // [m][k] tf32
    __shared__ uint32_t Ws[128 * GPAD];   // [n][k] tf32

    const int tid  = threadIdx.x;
    const int warp = tid >> 5;
    const int lane = tid & 31;
    const int g    = lane >> 2;
    const int tc   = lane & 3;
    const int wm   = (warp >> 1) * 32;
    const int wn   = (warp & 1) * 64;
    const int m0   = blockIdx.y * 128;
    const int n0   = blockIdx.x * 128;

    const int lrow = tid >> 1;
    const int lkof = (tid & 1) * 16;

    const uint32_t asb = smem_u32(As);
    const uint32_t wsb = smem_u32(Ws);
    // A-fragment lane offset: row (lane>>3 &1)*8 + (lane&7), khalf (lane>>4)*4
    const uint32_t lqA = 4u * ((((lane >> 3) & 1) * 8 + (lane & 7)) * GPAD + (lane >> 4) * 4);
    // B-fragment lane offset: ntile-sub (lane>>4), row lane&7, khalf (lane>>3 &1)*4
    const uint32_t lkB = 4u * (((lane >> 4) * 8 + (lane & 7)) * GPAD + ((lane >> 3) & 1) * 4);

    float acc[2][8][4];
#pragma unroll
    for (int mf = 0; mf < 2; mf++)
#pragma unroll
        for (int nf = 0; nf < 8; nf++)
#pragma unroll
            for (int i = 0; i < 4; i++) acc[mf][nf][i] = 0.0f;

    for (int k0 = 0; k0 < K; k0 += 32) {
        {
            const float* arow = &A[(size_t)(m0 + lrow) * K + k0 + lkof];
            const float* wrow = &W[(size_t)(n0 + lrow) * K + k0 + lkof];
#pragma unroll
            for (int j = 0; j < 16; j += 4) {
                float4 va = *reinterpret_cast<const float4*>(arow + j);
                As[lrow * GPAD + lkof + j + 0] = f2tf(va.x);
                As[lrow * GPAD + lkof + j + 1] = f2tf(va.y);
                As[lrow * GPAD + lkof + j + 2] = f2tf(va.z);
                As[lrow * GPAD + lkof + j + 3] = f2tf(va.w);
                float4 vw = *reinterpret_cast<const float4*>(wrow + j);
                Ws[lrow * GPAD + lkof + j + 0] = f2tf(vw.x);
                Ws[lrow * GPAD + lkof + j + 1] = f2tf(vw.y);
                Ws[lrow * GPAD + lkof + j + 2] = f2tf(vw.z);
                Ws[lrow * GPAD + lkof + j + 3] = f2tf(vw.w);
            }
        }
        __syncthreads();

#pragma unroll
        for (int kk = 0; kk < 4; kk++) {
            const uint32_t kbb = kk * 32;   // kb*4 bytes
            uint32_t a[2][4];
            ldsm4(a[0][0], a[0][1], a[0][2], a[0][3],
                  asb + 4u * (uint32_t)(wm * GPAD) + lqA + kbb);
            ldsm4(a[1][0], a[1][1], a[1][2], a[1][3],
                  asb + 4u * (uint32_t)((wm + 16) * GPAD) + lqA + kbb);
#pragma unroll
            for (int nf = 0; nf < 8; nf += 2) {
                uint32_t b00, b01, b10, b11;
                ldsm4(b00, b01, b10, b11,
                      wsb + 4u * (uint32_t)((wn + nf * 8) * GPAD) + lkB + kbb);
                mma_tf32(acc[0][nf], a[0][0], a[0][1], a[0][2], a[0][3], b00, b01);
                mma_tf32(acc[1][nf], a[1][0], a[1][1], a[1][2], a[1][3], b00, b01);
                mma_tf32(acc[0][nf + 1], a[0][0], a[0][1], a[0][2], a[0][3], b10, b11);
                mma_tf32(acc[1][nf + 1], a[1][0], a[1][1], a[1][2], a[1][3], b10, b11);
            }
        }
        __syncthreads();
    }

#pragma unroll
    for (int mf = 0; mf < 2; mf++) {
        const int r0 = m0 + wm + mf * 16 + g;
#pragma unroll
        for (int nf = 0; nf < 8; nf++) {
            const int cc = n0 + wn + nf * 8 + 2 * tc;
            float o0 = acc[mf][nf][0], o1 = acc[mf][nf][1];
            float o2 = acc[mf][nf][2], o3 = acc[mf][nf][3];
            if (round_out) {
                o0 = __uint_as_float(f2tf(o0));
                o1 = __uint_as_float(f2tf(o1));
                o2 = __uint_as_float(f2tf(o2));
                o3 = __uint_as_float(f2tf(o3));
            }
            *reinterpret_cast<float2*>(&C[(size_t)r0 * N + cc]) = make_float2(o0, o1);
            *reinterpret_cast<float2*>(&C[(size_t)(r0 + 8) * N + cc]) = make_float2(o2, o3);
        }
    }
}

// ---------------------------------------------------------------------------
// Flash attention, tf32 mma.sync. qkv holds tf32-exact fp32: K/V/Q staged via
// bare cp.async (K/V double-buffered, one sync/tile). Q/K fragments via
// ldmatrix.x4; V via scalar LDS (no 32-bit trans ldmatrix). exp via MUFU.
// ---------------------------------------------------------------------------
#define BR 128
#define BC 64
#define NT (LL / BC)
#define KP 68
#define VP 72
#define QW (BR * KP)    // 8704
#define KW (BC * KP)    // 4352
#define VW (BC * VP)    // 4608
#define ASM_WORDS (QW + 2 * KW + 2 * VW)   // 26624
#define ASM_BYTES (ASM_WORDS * 4)          // 106496 -> 2 CTAs/SM

__global__ __launch_bounds__(256, 2) void attn_tf32_kernel(
    const float* __restrict__ qkv, float* __restrict__ ctx)
{
    extern __shared__ uint32_t sm[];
    const uint32_t sb = smem_u32(sm);

    const int tid  = threadIdx.x;
    const int warp = tid >> 5;
    const int lane = tid & 31;
    const int g    = lane >> 2;
    const int tc   = lane & 3;
    const int wm   = warp * 16;

    const int bh = blockIdx.y;
    const int b  = bh >> 3;
    const int h  = bh & 7;
    const int q0 = blockIdx.x * BR;

    const float* base = qkv + (size_t)b * LL * QKVN + h * DKK;

    // loader mapping for K/V tiles: 4 threads/row, 16 floats each
    const int lr = tid >> 2;            // 0..63
    const int lc = (tid & 3) * 16;      // 0,16,32,48

    // ldmatrix lane-constant offsets (bytes)
    const uint32_t lqQ = 4u * ((((lane >> 3) & 1) * 8 + (lane & 7)) * KP + (lane >> 4) * 4);
    const uint32_t lkK = 4u * (((lane >> 4) * 8 + (lane & 7)) * KP + ((lane >> 3) & 1) * 4);
    const uint32_t qfrag_base = sb + 4u * (uint32_t)(wm * KP) + lqQ;

    // ---- Prologue: cp.async Q tile + K/V tile 0 ----
    {
        const int r  = tid >> 1;
        const int c0 = (tid & 1) * 32;
        const float* qrow = base + (size_t)(q0 + r) * QKVN;
#pragma unroll
        for (int j = 0; j < 8; j++)
            cp16s(sb + 4 * (r * KP + c0 + 4 * j), qrow + c0 + 4 * j);

        const float* krow = base + (size_t)lr * QKVN + DD;
        const float* vrow = krow + DD;
#pragma unroll
        for (int j = 0; j < 4; j++) {
            cp16s(sb + 4 * (QW + lr * KP + lc + 4 * j), krow + lc + 4 * j);
            cp16s(sb + 4 * (QW + 2 * KW + lr * VP + lc + 4 * j), vrow + lc + 4 * j);
        }
        asm volatile("cp.async.commit_group;");
        asm volatile("cp.async.wait_group 0;");
    }
    __syncthreads();

    float oa[8][4];
#pragma unroll
    for (int n = 0; n < 8; n++)
#pragma unroll
        for (int i = 0; i < 4; i++) oa[n][i] = 0.0f;
    float m0 = -1e30f, m1 = -1e30f;   // running max in RAW score domain
    float l0 = 0.0f,  l1 = 0.0f;

    const int srcA = g * 4 + (tc >> 1);
    const int srcB = srcA + 2;
    const bool odd = (tc & 1);

    for (int t = 0; t < NT; t++) {
        const bool pf = (t + 1 < NT);
        const uint32_t ksb = sb + 4u * (uint32_t)(QW + (t & 1) * KW);
        const uint32_t* Vs = sm + QW + 2 * KW + (t & 1) * VW;

        // Issue next tile's K/V into the alternate stage.
        if (pf) {
            const float* krow = base + (size_t)((t + 1) * BC + lr) * QKVN + DD;
            const float* vrow = krow + DD;
            const uint32_t kd = sb + 4 * (QW + ((t + 1) & 1) * KW);
            const uint32_t vd = sb + 4 * (QW + 2 * KW + ((t + 1) & 1) * VW);
#pragma unroll
            for (int j = 0; j < 4; j++) {
                cp16s(kd + 4 * (lr * KP + lc + 4 * j), krow + lc + 4 * j);
                cp16s(vd + 4 * (lr * VP + lc + 4 * j), vrow + lc + 4 * j);
            }
            asm volatile("cp.async.commit_group;");
        }

        // S = Q @ K^T : 16x64 per warp; fragments via ldmatrix
        float sa[8][4];
#pragma unroll
        for (int n = 0; n < 8; n++)
#pragma unroll
            for (int i = 0; i < 4; i++) sa[n][i] = 0.0f;

        const uint32_t kfrag_base = ksb + lkK;
#pragma unroll
        for (int kk = 0; kk < 8; kk++) {
            const uint32_t kbb = kk * 32;   // kb words * 4 bytes
            uint32_t a0, a1, a2, a3;
            ldsm4(a0, a1, a2, a3, qfrag_base + kbb);
#pragma unroll
            for (int nn = 0; nn < 8; nn += 2) {
                uint32_t b00, b01, b10, b11;
                ldsm4(b00, b01, b10, b11,
                      kfrag_base + (uint32_t)(nn * 8 * KP * 4) + kbb);
                mma_tf32(sa[nn], a0, a1, a2, a3, b00, b01);
                mma_tf32(sa[nn + 1], a0, a1, a2, a3, b10, b11);
            }
        }

        // Online softmax (base-2, scale folded into exp argument).
        float mx0 = -1e30f, mx1 = -1e30f;
#pragma unroll
        for (int n = 0; n < 8; n++) {
            mx0 = fmaxf(mx0, fmaxf(sa[n][0], sa[n][1]));
            mx1 = fmaxf(mx1, fmaxf(sa[n][2], sa[n][3]));
        }
        mx0 = fmaxf(mx0, __shfl_xor_sync(0xffffffffu, mx0, 1));
        mx0 = fmaxf(mx0, __shfl_xor_sync(0xffffffffu, mx0, 2));
        mx1 = fmaxf(mx1, __shfl_xor_sync(0xffffffffu, mx1, 1));
        mx1 = fmaxf(mx1, __shfl_xor_sync(0xffffffffu, mx1, 2));

        const bool upd = !__all_sync(0xffffffffu, (mx0 <= m0) & (mx1 <= m1));
        if (upd) {
            float mn0 = fmaxf(m0, mx0);
            float mn1 = fmaxf(m1, mx1);
            float alpha0 = ex2(CC * (m0 - mn0));
            float alpha1 = ex2(CC * (m1 - mn1));
            m0 = mn0; m1 = mn1;
            l0 *= alpha0;
            l1 *= alpha1;
#pragma unroll
            for (int n = 0; n < 8; n++) {
                oa[n][0] *= alpha0; oa[n][1] *= alpha0;
                oa[n][2] *= alpha1; oa[n][3] *= alpha1;
            }
        }

        const float nc0 = -CC * m0;
        const float nc1 = -CC * m1;
        float sum0 = 0.0f, sum1 = 0.0f;
#pragma unroll
        for (int n = 0; n < 8; n++) {
            float p0 = ex2(fmaf(CC, sa[n][0], nc0));
            float p1 = ex2(fmaf(CC, sa[n][1], nc0));
            float p2 = ex2(fmaf(CC, sa[n][2], nc1));
            float p3 = ex2(fmaf(CC, sa[n][3], nc1));
            sum0 += p0 + p1;
            sum1 += p2 + p3;
            sa[n][0] = p0; sa[n][1] = p1; sa[n][2] = p2; sa[n][3] = p3;
        }
        l0 += sum0;
        l1 += sum1;

        // O += P @ V. P fragments from S fragments via shuffles.
#pragma unroll
        for (int kk = 0; kk < 8; kk++) {
            float v00 = __shfl_sync(0xffffffffu, sa[kk][0], srcA);
            float v01 = __shfl_sync(0xffffffffu, sa[kk][1], srcA);
            float v10 = __shfl_sync(0xffffffffu, sa[kk][2], srcA);
            float v11 = __shfl_sync(0xffffffffu, sa[kk][3], srcA);
            float w00 = __shfl_sync(0xffffffffu, sa[kk][0], srcB);
            float w01 = __shfl_sync(0xffffffffu, sa[kk][1], srcB);
            float w10 = __shfl_sync(0xffffffffu, sa[kk][2], srcB);
            float w11 = __shfl_sync(0xffffffffu, sa[kk][3], srcB);
            uint32_t pa0 = f2tf(odd ? v01 : v00);
            uint32_t pa1 = f2tf(odd ? v11 : v10);
            uint32_t pa2 = f2tf(odd ? w01 : w00);
            uint32_t pa3 = f2tf(odd ? w11 : w10);
            const int kb = kk * 8;
#pragma unroll
            for (int n = 0; n < 8; n++) {
                uint32_t b0 = Vs[(kb + tc) * VP + n * 8 + g];
                uint32_t b1 = Vs[(kb + tc + 4) * VP + n * 8 + g];
                mma_tf32(oa[n], pa0, pa1, pa2, pa3, b0, b1);
            }
        }

        if (pf) { asm volatile("cp.async.wait_group 0;"); }
        __syncthreads();
    }

    // Finalize l across the quad, normalize, write ctx.
    l0 += __shfl_xor_sync(0xffffffffu, l0, 1);
    l0 += __shfl_xor_sync(0xffffffffu, l0, 2);
    l1 += __shfl_xor_sync(0xffffffffu, l1, 1);
    l1 += __shfl_xor_sync(0xffffffffu, l1, 2);
    float inv0 = 1.0f / l0;
    float inv1 = 1.0f / l1;

    const int r0 = q0 + wm + g;
    const int r1 = r0 + 8;
#pragma unroll
    for (int n = 0; n < 8; n++) {
        *reinterpret_cast<float2*>(
            &ctx[(size_t)(b * LL + r0) * DD + h * DKK + n * 8 + 2 * tc]) =
            make_float2(oa[n][0] * inv0, oa[n][1] * inv0);
        *reinterpret_cast<float2*>(
            &ctx[(size_t)(b * LL + r1) * DD + h * DKK + n * 8 + 2 * tc]) =
            make_float2(oa[n][2] * inv1, oa[n][3] * inv1);
    }
}

// ---------------------------------------------------------------------------
extern "C" void kernel_launch(void* const* d_in, const int* in_sizes, int n_in,
                              void* d_out, int out_size)
{
    const float* x     = (const float*)d_in[0];   // [B, L, D]
    const float* w_qkv = (const float*)d_in[1];   // [3D, D]
    const float* w_o   = (const float*)d_in[2];   // [D, D]
    float* out = (float*)d_out;                   // [B, L, D]

    float* qkv_p = nullptr;
    float* ctx_p = nullptr;
    cudaGetSymbolAddress((void**)&qkv_p, g_qkv);
    cudaGetSymbolAddress((void**)&ctx_p, g_ctx);
    cudaFuncSetAttribute(attn_tf32_kernel, cudaFuncAttributeMaxDynamicSharedMemorySize, ASM_BYTES);

    // 1) qkv = x @ w_qkv^T : [8192, 1536], outputs rounded to tf32-exact
    {
        dim3 grid(QKVN / 128, MROWS / 128);
        gemm_tf32_kernel<<<grid, 256>>>(x, w_qkv, qkv_p, MROWS, QKVN, DD, 1);
    }
    // 2) attention -> ctx
    {
        dim3 grid(LL / BR, BB * HH);
        attn_tf32_kernel<<<grid, 256, ASM_BYTES>>>(qkv_p, ctx_p);
    }
    // 3) out = ctx @ w_o^T : [8192, 512], plain fp32 output
    {
        dim3 grid(DD / 128, MROWS / 128);
        gemm_tf32_kernel<<<grid, 256>>>(ctx_p, w_o, out, MROWS, DD, DD, 0);
    }
}

// round 10
// speedup vs baseline: 3.2169x; 1.8377x over previous
#include <cuda_runtime.h>
#include <cuda_fp16.h>
#include <math.h>
#include <stdint.h>

#define BB 2
#define LL 4096
#define DD 512
#define HH 8
#define DKK 64
#define MROWS (BB*LL)          // 8192
#define QKVN (3*DD)            // 1536
// softmax scale (1/sqrt(64) * log2(e)); applied inside exp2
#define CC (0.125f * 1.4426950408889634f)

// Scratch (allocation-free rule: __device__ globals)
__device__ __half g_qkv[(size_t)MROWS * QKVN];  // [B*L, 3*D] fp16
__device__ float  g_ctx[(size_t)MROWS * DD];    // [B*L, D] fp32

// ---------------------------------------------------------------------------
// Helpers
// ---------------------------------------------------------------------------
__device__ __forceinline__ uint32_t f2tf(float x) {
    uint32_t u;
    asm("cvt.rna.tf32.f32 %0, %1;" : "=r"(u) : "f"(x));
    return u;
}

__device__ __forceinline__ float ex2(float x) {
    float y;
    asm("ex2.approx.ftz.f32 %0, %1;" : "=f"(y) : "f"(x));
    return y;
}

// pack two fp32 -> fp16x2 (lo = first arg, hi = second arg)
__device__ __forceinline__ uint32_t pack_h2(float lo, float hi) {
    uint32_t r;
    asm("cvt.rn.f16x2.f32 %0, %1, %2;" : "=r"(r) : "f"(hi), "f"(lo));
    return r;
}

__device__ __forceinline__ void mma_tf32(float c[4],
    uint32_t a0, uint32_t a1, uint32_t a2, uint32_t a3,
    uint32_t b0, uint32_t b1)
{
    asm volatile(
        "mma.sync.aligned.m16n8k8.row.col.f32.tf32.tf32.f32 "
        "{%0,%1,%2,%3}, {%4,%5,%6,%7}, {%8,%9}, {%0,%1,%2,%3};"
        : "+f"(c[0]), "+f"(c[1]), "+f"(c[2]), "+f"(c[3])
        : "r"(a0), "r"(a1), "r"(a2), "r"(a3), "r"(b0), "r"(b1));
}

__device__ __forceinline__ void mma_f16(float c[4],
    uint32_t a0, uint32_t a1, uint32_t a2, uint32_t a3,
    uint32_t b0, uint32_t b1)
{
    asm volatile(
        "mma.sync.aligned.m16n8k16.row.col.f32.f16.f16.f32 "
        "{%0,%1,%2,%3}, {%4,%5,%6,%7}, {%8,%9}, {%0,%1,%2,%3};"
        : "+f"(c[0]), "+f"(c[1]), "+f"(c[2]), "+f"(c[3])
        : "r"(a0), "r"(a1), "r"(a2), "r"(a3), "r"(b0), "r"(b1));
}

__device__ __forceinline__ void ldsm4(uint32_t& r0, uint32_t& r1,
                                      uint32_t& r2, uint32_t& r3, uint32_t addr)
{
    asm volatile("ldmatrix.sync.aligned.m8n8.x4.shared.b16 {%0,%1,%2,%3}, [%4];"
                 : "=r"(r0), "=r"(r1), "=r"(r2), "=r"(r3) : "r"(addr));
}

__device__ __forceinline__ void ldsm4t(uint32_t& r0, uint32_t& r1,
                                       uint32_t& r2, uint32_t& r3, uint32_t addr)
{
    asm volatile("ldmatrix.sync.aligned.m8n8.x4.trans.shared.b16 {%0,%1,%2,%3}, [%4];"
                 : "=r"(r0), "=r"(r1), "=r"(r2), "=r"(r3) : "r"(addr));
}

__device__ __forceinline__ uint32_t smem_u32(const void* p) {
    uint32_t a;
    asm("{ .reg .u64 t; cvta.to.shared.u64 t, %1; cvt.u32.u64 %0, t; }"
        : "=r"(a) : "l"(p));
    return a;
}

__device__ __forceinline__ void cp16s(uint32_t smem_addr, const void* gptr) {
    asm volatile("cp.async.cg.shared.global [%0], [%1], 16;"
                 :: "r"(smem_addr), "l"(gptr));
}

// ---------------------------------------------------------------------------
// tf32 GEMM: C[M,N] = A[M,K] @ W[N,K]^T. 128x128 tiles, BK=32, 8 warps
// (4m x 2n), warp tile 32x64. Fragment loads via ldmatrix.x4.
// half_out != 0 -> C is __half*, outputs written as packed fp16.
// ---------------------------------------------------------------------------
#define GPAD 36   // 32 k + 4 pad (144B rows, 16B aligned)

__global__ __launch_bounds__(256, 2) void gemm_tf32_kernel(
    const float* __restrict__ A, const float* __restrict__ W,
    void* __restrict__ Cv, int M, int N, int K, int half_out)
{
    __shared__ uint32_t As[128 * GPAD];
    __shared__ uint32_t Ws[128 * GPAD];

    const int tid  = threadIdx.x;
    const int warp = tid >> 5;
    const int lane = tid & 31;
    const int g    = lane >> 2;
    const int tc   = lane & 3;
    const int wm   = (warp >> 1) * 32;
    const int wn   = (warp & 1) * 64;
    const int m0   = blockIdx.y * 128;
    const int n0   = blockIdx.x * 128;

    const int lrow = tid >> 1;
    const int lkof = (tid & 1) * 16;

    const uint32_t asb = smem_u32(As);
    const uint32_t wsb = smem_u32(Ws);
    const uint32_t lqA = 4u * ((((lane >> 3) & 1) * 8 + (lane & 7)) * GPAD + (lane >> 4) * 4);
    const uint32_t lkB = 4u * (((lane >> 4) * 8 + (lane & 7)) * GPAD + ((lane >> 3) & 1) * 4);

    float acc[2][8][4];
#pragma unroll
    for (int mf = 0; mf < 2; mf++)
#pragma unroll
        for (int nf = 0; nf < 8; nf++)
#pragma unroll
            for (int i = 0; i < 4; i++) acc[mf][nf][i] = 0.0f;

    for (int k0 = 0; k0 < K; k0 += 32) {
        {
            const float* arow = &A[(size_t)(m0 + lrow) * K + k0 + lkof];
            const float* wrow = &W[(size_t)(n0 + lrow) * K + k0 + lkof];
#pragma unroll
            for (int j = 0; j < 16; j += 4) {
                float4 va = *reinterpret_cast<const float4*>(arow + j);
                As[lrow * GPAD + lkof + j + 0] = f2tf(va.x);
                As[lrow * GPAD + lkof + j + 1] = f2tf(va.y);
                As[lrow * GPAD + lkof + j + 2] = f2tf(va.z);
                As[lrow * GPAD + lkof + j + 3] = f2tf(va.w);
                float4 vw = *reinterpret_cast<const float4*>(wrow + j);
                Ws[lrow * GPAD + lkof + j + 0] = f2tf(vw.x);
                Ws[lrow * GPAD + lkof + j + 1] = f2tf(vw.y);
                Ws[lrow * GPAD + lkof + j + 2] = f2tf(vw.z);
                Ws[lrow * GPAD + lkof + j + 3] = f2tf(vw.w);
            }
        }
        __syncthreads();

#pragma unroll
        for (int kk = 0; kk < 4; kk++) {
            const uint32_t kbb = kk * 32;
            uint32_t a[2][4];
            ldsm4(a[0][0], a[0][1], a[0][2], a[0][3],
                  asb + 4u * (uint32_t)(wm * GPAD) + lqA + kbb);
            ldsm4(a[1][0], a[1][1], a[1][2], a[1][3],
                  asb + 4u * (uint32_t)((wm + 16) * GPAD) + lqA + kbb);
#pragma unroll
            for (int nf = 0; nf < 8; nf += 2) {
                uint32_t b00, b01, b10, b11;
                ldsm4(b00, b01, b10, b11,
                      wsb + 4u * (uint32_t)((wn + nf * 8) * GPAD) + lkB + kbb);
                mma_tf32(acc[0][nf], a[0][0], a[0][1], a[0][2], a[0][3], b00, b01);
                mma_tf32(acc[1][nf], a[1][0], a[1][1], a[1][2], a[1][3], b00, b01);
                mma_tf32(acc[0][nf + 1], a[0][0], a[0][1], a[0][2], a[0][3], b10, b11);
                mma_tf32(acc[1][nf + 1], a[1][0], a[1][1], a[1][2], a[1][3], b10, b11);
            }
        }
        __syncthreads();
    }

#pragma unroll
    for (int mf = 0; mf < 2; mf++) {
        const int r0 = m0 + wm + mf * 16 + g;
#pragma unroll
        for (int nf = 0; nf < 8; nf++) {
            const int cc = n0 + wn + nf * 8 + 2 * tc;
            if (half_out) {
                __half* Ch = (__half*)Cv;
                *reinterpret_cast<uint32_t*>(&Ch[(size_t)r0 * N + cc]) =
                    pack_h2(acc[mf][nf][0], acc[mf][nf][1]);
                *reinterpret_cast<uint32_t*>(&Ch[(size_t)(r0 + 8) * N + cc]) =
                    pack_h2(acc[mf][nf][2], acc[mf][nf][3]);
            } else {
                float* Cf = (float*)Cv;
                *reinterpret_cast<float2*>(&Cf[(size_t)r0 * N + cc]) =
                    make_float2(acc[mf][nf][0], acc[mf][nf][1]);
                *reinterpret_cast<float2*>(&Cf[(size_t)(r0 + 8) * N + cc]) =
                    make_float2(acc[mf][nf][2], acc[mf][nf][3]);
            }
        }
    }
}

// ---------------------------------------------------------------------------
// Flash attention, fp16 m16n8k16 (fp32 accumulate). qkv is fp16: staged by
// bare cp.async (K/V double-buffered, one sync/tile). Q/K fragments via
// ldmatrix.x4; V via ldmatrix.x4.trans; P packs lane-locally (no shuffles).
// ---------------------------------------------------------------------------
#define BR 128
#define BC 64
#define NT (LL / BC)
#define QPH 72                 // row stride in halves (144B, 16B aligned)
#define SB_K (BR * QPH * 2)    // 18432 B: Q tile
#define KSTB (BC * QPH * 2)    // 9216 B per K/V stage
#define SB_V (SB_K + 2 * KSTB)
#define ASM_BYTES (SB_V + 2 * KSTB)   // 55296 B -> 2 CTAs/SM

__global__ __launch_bounds__(256, 2) void attn_f16_kernel(
    const __half* __restrict__ qkv, float* __restrict__ ctx)
{
    extern __shared__ uint32_t sm[];
    const uint32_t sb = smem_u32(sm);

    const int tid  = threadIdx.x;
    const int warp = tid >> 5;
    const int lane = tid & 31;
    const int g    = lane >> 2;
    const int tc   = lane & 3;
    const int wm   = warp * 16;

    const int bh = blockIdx.y;
    const int b  = bh >> 3;
    const int h  = bh & 7;
    const int q0 = blockIdx.x * BR;

    const __half* base = qkv + (size_t)b * LL * QKVN + h * DKK;

    // K/V loader mapping: 4 threads/row, 16 halves (32B) each -> 2 cp16
    const int lr  = tid >> 2;           // 0..63
    const int lc2 = (tid & 3) * 16;     // halves: 0,16,32,48

    // ldmatrix lane-offsets (bytes)
    const uint32_t lqQ = (uint32_t)(((wm + (lane & 15)) * QPH + (lane >> 4) * 8) * 2);
    const uint32_t lkK = (uint32_t)((((lane & 7) + (lane >> 4) * 8) * QPH
                                    + ((lane >> 3) & 1) * 8) * 2);
    const uint32_t lvV = (uint32_t)((((lane & 7) + ((lane >> 3) & 1) * 8) * QPH
                                    + (lane >> 4) * 8) * 2);

    // ---- Prologue: cp.async Q tile + K/V tile 0 ----
    {
        const int r   = tid >> 1;
        const int c0h = (tid & 1) * 32;
        const __half* qrow = base + (size_t)(q0 + r) * QKVN;
#pragma unroll
        for (int j = 0; j < 4; j++)
            cp16s(sb + (uint32_t)((r * QPH + c0h + 8 * j) * 2), qrow + c0h + 8 * j);

        const __half* krow = base + (size_t)lr * QKVN + DD;
        const __half* vrow = krow + DD;
#pragma unroll
        for (int j = 0; j < 2; j++) {
            cp16s(sb + SB_K + (uint32_t)((lr * QPH + lc2 + 8 * j) * 2), krow + lc2 + 8 * j);
            cp16s(sb + SB_V + (uint32_t)((lr * QPH + lc2 + 8 * j) * 2), vrow + lc2 + 8 * j);
        }
        asm volatile("cp.async.commit_group;");
        asm volatile("cp.async.wait_group 0;");
    }
    __syncthreads();

    float oa[8][4];
#pragma unroll
    for (int n = 0; n < 8; n++)
#pragma unroll
        for (int i = 0; i < 4; i++) oa[n][i] = 0.0f;
    float m0 = -1e30f, m1 = -1e30f;   // running max, RAW score domain
    float l0 = 0.0f,  l1 = 0.0f;

    for (int t = 0; t < NT; t++) {
        const bool pf = (t + 1 < NT);
        const uint32_t ksb = sb + SB_K + (uint32_t)((t & 1) * KSTB);
        const uint32_t vsb = sb + SB_V + (uint32_t)((t & 1) * KSTB);

        // Issue next tile's K/V into the alternate stage.
        if (pf) {
            const __half* krow = base + (size_t)((t + 1) * BC + lr) * QKVN + DD;
            const __half* vrow = krow + DD;
            const uint32_t kd = sb + SB_K + (uint32_t)(((t + 1) & 1) * KSTB);
            const uint32_t vd = sb + SB_V + (uint32_t)(((t + 1) & 1) * KSTB);
#pragma unroll
            for (int j = 0; j < 2; j++) {
                cp16s(kd + (uint32_t)((lr * QPH + lc2 + 8 * j) * 2), krow + lc2 + 8 * j);
                cp16s(vd + (uint32_t)((lr * QPH + lc2 + 8 * j) * 2), vrow + lc2 + 8 * j);
            }
            asm volatile("cp.async.commit_group;");
        }

        // S = Q @ K^T : 16x64 per warp, fp16 k16
        float sa[8][4];
#pragma unroll
        for (int n = 0; n < 8; n++)
#pragma unroll
            for (int i = 0; i < 4; i++) sa[n][i] = 0.0f;

#pragma unroll
        for (int kk = 0; kk < 4; kk++) {
            uint32_t a0, a1, a2, a3;
            ldsm4(a0, a1, a2, a3, sb + lqQ + (uint32_t)(kk * 32));
#pragma unroll
            for (int nb = 0; nb < 4; nb++) {
                uint32_t b00, b01, b10, b11;
                ldsm4(b00, b01, b10, b11,
                      ksb + lkK + (uint32_t)((nb * 16 * QPH + kk * 16) * 2));
                mma_f16(sa[2 * nb], a0, a1, a2, a3, b00, b01);
                mma_f16(sa[2 * nb + 1], a0, a1, a2, a3, b10, b11);
            }
        }

        // Online softmax (base-2, scale folded into exp argument).
        float mx0 = -1e30f, mx1 = -1e30f;
#pragma unroll
        for (int n = 0; n < 8; n++) {
            mx0 = fmaxf(mx0, fmaxf(sa[n][0], sa[n][1]));
            mx1 = fmaxf(mx1, fmaxf(sa[n][2], sa[n][3]));
        }
        mx0 = fmaxf(mx0, __shfl_xor_sync(0xffffffffu, mx0, 1));
        mx0 = fmaxf(mx0, __shfl_xor_sync(0xffffffffu, mx0, 2));
        mx1 = fmaxf(mx1, __shfl_xor_sync(0xffffffffu, mx1, 1));
        mx1 = fmaxf(mx1, __shfl_xor_sync(0xffffffffu, mx1, 2));

        const bool upd = !__all_sync(0xffffffffu, (mx0 <= m0) & (mx1 <= m1));
        if (upd) {
            float mn0 = fmaxf(m0, mx0);
            float mn1 = fmaxf(m1, mx1);
            float alpha0 = ex2(CC * (m0 - mn0));
            float alpha1 = ex2(CC * (m1 - mn1));
            m0 = mn0; m1 = mn1;
            l0 *= alpha0;
            l1 *= alpha1;
#pragma unroll
            for (int n = 0; n < 8; n++) {
                oa[n][0] *= alpha0; oa[n][1] *= alpha0;
                oa[n][2] *= alpha1; oa[n][3] *= alpha1;
            }
        }

        const float nc0 = -CC * m0;
        const float nc1 = -CC * m1;
        float sum0 = 0.0f, sum1 = 0.0f;
#pragma unroll
        for (int n = 0; n < 8; n++) {
            float p0 = ex2(fmaf(CC, sa[n][0], nc0));
            float p1 = ex2(fmaf(CC, sa[n][1], nc0));
            float p2 = ex2(fmaf(CC, sa[n][2], nc1));
            float p3 = ex2(fmaf(CC, sa[n][3], nc1));
            sum0 += p0 + p1;
            sum1 += p2 + p3;
            sa[n][0] = p0; sa[n][1] = p1; sa[n][2] = p2; sa[n][3] = p3;
        }
        l0 += sum0;
        l1 += sum1;

        // O += P @ V : fp16 k16, P packed lane-locally, V via ldsm.trans
#pragma unroll
        for (int kk = 0; kk < 4; kk++) {
            uint32_t a0 = pack_h2(sa[2 * kk][0],     sa[2 * kk][1]);
            uint32_t a1 = pack_h2(sa[2 * kk][2],     sa[2 * kk][3]);
            uint32_t a2 = pack_h2(sa[2 * kk + 1][0], sa[2 * kk + 1][1]);
            uint32_t a3 = pack_h2(sa[2 * kk + 1][2], sa[2 * kk + 1][3]);
#pragma unroll
            for (int nb = 0; nb < 4; nb++) {
                uint32_t b00, b01, b10, b11;
                ldsm4t(b00, b01, b10, b11,
                       vsb + lvV + (uint32_t)((kk * 16 * QPH + nb * 16) * 2));
                mma_f16(oa[2 * nb], a0, a1, a2, a3, b00, b01);
                mma_f16(oa[2 * nb + 1], a0, a1, a2, a3, b10, b11);
            }
        }

        if (pf) { asm volatile("cp.async.wait_group 0;"); }
        __syncthreads();
    }

    // Finalize l across the quad, normalize, write ctx.
    l0 += __shfl_xor_sync(0xffffffffu, l0, 1);
    l0 += __shfl_xor_sync(0xffffffffu, l0, 2);
    l1 += __shfl_xor_sync(0xffffffffu, l1, 1);
    l1 += __shfl_xor_sync(0xffffffffu, l1, 2);
    float inv0 = 1.0f / l0;
    float inv1 = 1.0f / l1;

    const int r0 = q0 + wm + g;
    const int r1 = r0 + 8;
#pragma unroll
    for (int n = 0; n < 8; n++) {
        *reinterpret_cast<float2*>(
            &ctx[(size_t)(b * LL + r0) * DD + h * DKK + n * 8 + 2 * tc]) =
            make_float2(oa[n][0] * inv0, oa[n][1] * inv0);
        *reinterpret_cast<float2*>(
            &ctx[(size_t)(b * LL + r1) * DD + h * DKK + n * 8 + 2 * tc]) =
            make_float2(oa[n][2] * inv1, oa[n][3] * inv1);
    }
}

// ---------------------------------------------------------------------------
extern "C" void kernel_launch(void* const* d_in, const int* in_sizes, int n_in,
                              void* d_out, int out_size)
{
    const float* x     = (const float*)d_in[0];   // [B, L, D]
    const float* w_qkv = (const float*)d_in[1];   // [3D, D]
    const float* w_o   = (const float*)d_in[2];   // [D, D]
    float* out = (float*)d_out;                   // [B, L, D]

    __half* qkv_p = nullptr;
    float*  ctx_p = nullptr;
    cudaGetSymbolAddress((void**)&qkv_p, g_qkv);
    cudaGetSymbolAddress((void**)&ctx_p, g_ctx);
    cudaFuncSetAttribute(attn_f16_kernel, cudaFuncAttributeMaxDynamicSharedMemorySize, ASM_BYTES);

    // 1) qkv = x @ w_qkv^T : [8192, 1536], fp16 output
    {
        dim3 grid(QKVN / 128, MROWS / 128);
        gemm_tf32_kernel<<<grid, 256>>>(x, w_qkv, qkv_p, MROWS, QKVN, DD, 1);
    }
    // 2) attention -> ctx (fp32)
    {
        dim3 grid(LL / BR, BB * HH);
        attn_f16_kernel<<<grid, 256, ASM_BYTES>>>(qkv_p, ctx_p);
    }
    // 3) out = ctx @ w_o^T : [8192, 512], fp32 output
    {
        dim3 grid(DD / 128, MROWS / 128);
        gemm_tf32_kernel<<<grid, 256>>>(ctx_p, w_o, out, MROWS, DD, DD, 0);
    }
}

// round 11
// speedup vs baseline: 3.5447x; 1.1019x over previous
#include <cuda_runtime.h>
#include <cuda_fp16.h>
#include <math.h>
#include <stdint.h>

#define BB 2
#define LL 4096
#define DD 512
#define HH 8
#define DKK 64
#define MROWS (BB*LL)          // 8192
#define QKVN (3*DD)            // 1536
// softmax scale (1/sqrt(64) * log2(e)); applied inside exp2
#define CC (0.125f * 1.4426950408889634f)

// Scratch (allocation-free rule: __device__ globals)
__device__ __half g_qkv[(size_t)MROWS * QKVN];  // [B*L, 3*D] fp16
__device__ __half g_ctx[(size_t)MROWS * DD];    // [B*L, D]   fp16

// ---------------------------------------------------------------------------
// Helpers
// ---------------------------------------------------------------------------
__device__ __forceinline__ float ex2(float x) {
    float y;
    asm("ex2.approx.ftz.f32 %0, %1;" : "=f"(y) : "f"(x));
    return y;
}

// pack two fp32 -> fp16x2 (lo = first arg, hi = second arg)
__device__ __forceinline__ uint32_t pack_h2(float lo, float hi) {
    uint32_t r;
    asm("cvt.rn.f16x2.f32 %0, %1, %2;" : "=r"(r) : "f"(hi), "f"(lo));
    return r;
}

__device__ __forceinline__ void mma_f16(float c[4],
    uint32_t a0, uint32_t a1, uint32_t a2, uint32_t a3,
    uint32_t b0, uint32_t b1)
{
    asm volatile(
        "mma.sync.aligned.m16n8k16.row.col.f32.f16.f16.f32 "
        "{%0,%1,%2,%3}, {%4,%5,%6,%7}, {%8,%9}, {%0,%1,%2,%3};"
        : "+f"(c[0]), "+f"(c[1]), "+f"(c[2]), "+f"(c[3])
        : "r"(a0), "r"(a1), "r"(a2), "r"(a3), "r"(b0), "r"(b1));
}

__device__ __forceinline__ void ldsm4(uint32_t& r0, uint32_t& r1,
                                      uint32_t& r2, uint32_t& r3, uint32_t addr)
{
    asm volatile("ldmatrix.sync.aligned.m8n8.x4.shared.b16 {%0,%1,%2,%3}, [%4];"
                 : "=r"(r0), "=r"(r1), "=r"(r2), "=r"(r3) : "r"(addr));
}

__device__ __forceinline__ void ldsm4t(uint32_t& r0, uint32_t& r1,
                                       uint32_t& r2, uint32_t& r3, uint32_t addr)
{
    asm volatile("ldmatrix.sync.aligned.m8n8.x4.trans.shared.b16 {%0,%1,%2,%3}, [%4];"
                 : "=r"(r0), "=r"(r1), "=r"(r2), "=r"(r3) : "r"(addr));
}

__device__ __forceinline__ uint32_t smem_u32(const void* p) {
    uint32_t a;
    asm("{ .reg .u64 t; cvta.to.shared.u64 t, %1; cvt.u32.u64 %0, t; }"
        : "=r"(a) : "l"(p));
    return a;
}

__device__ __forceinline__ void cp16s(uint32_t smem_addr, const void* gptr) {
    asm volatile("cp.async.cg.shared.global [%0], [%1], 16;"
                 :: "r"(smem_addr), "l"(gptr));
}

// ---------------------------------------------------------------------------
// fp16 GEMM (m16n8k16, fp32 accum): C[M,N] = A[M,K] @ W[N,K]^T.
// 128x128 tiles, BK=32, 8 warps (4m x 2n), warp tile 32x64.
// A: fp32 (cvt at staging) or fp16 (bare cp.async) per a_half flag.
// W: fp32, cvt at staging. C: fp16 or fp32 per half_out flag.
// ---------------------------------------------------------------------------
#define GH 40   // halves per smem row (80 B stride; ldsm-conflict-free)

__global__ __launch_bounds__(256, 2) void gemm_f16_kernel(
    const void* __restrict__ Av, const float* __restrict__ W,
    void* __restrict__ Cv, int M, int N, int K, int a_half, int half_out)
{
    __shared__ __half Ah[128 * GH];
    __shared__ __half Wh[128 * GH];

    const int tid  = threadIdx.x;
    const int warp = tid >> 5;
    const int lane = tid & 31;
    const int g    = lane >> 2;
    const int tc   = lane & 3;
    const int wm   = (warp >> 1) * 32;
    const int wn   = (warp & 1) * 64;
    const int m0   = blockIdx.y * 128;
    const int n0   = blockIdx.x * 128;

    const int lrow = tid >> 1;         // 0..127
    const int lkh  = (tid & 1) * 16;   // half-offset 0 / 16

    const uint32_t asb = smem_u32(Ah);
    const uint32_t wsb = smem_u32(Wh);
    // verified fragment addressing (same pattern as attention kernel)
    const uint32_t lqA = (uint32_t)(((lane & 15) * GH + (lane >> 4) * 8) * 2);
    const uint32_t lkB = (uint32_t)((((lane & 7) + (lane >> 4) * 8) * GH
                                    + ((lane >> 3) & 1) * 8) * 2);

    float acc[2][8][4];
#pragma unroll
    for (int mf = 0; mf < 2; mf++)
#pragma unroll
        for (int nf = 0; nf < 8; nf++)
#pragma unroll
            for (int i = 0; i < 4; i++) acc[mf][nf][i] = 0.0f;

    for (int k0 = 0; k0 < K; k0 += 32) {
        // ---- stage W (fp32 -> fp16) ----
        {
            const float* wrow = &W[(size_t)(n0 + lrow) * K + k0 + lkh];
            uint32_t u[8];
#pragma unroll
            for (int j = 0; j < 4; j++) {
                float4 v = *reinterpret_cast<const float4*>(wrow + j * 4);
                u[2 * j]     = pack_h2(v.x, v.y);
                u[2 * j + 1] = pack_h2(v.z, v.w);
            }
            uint32_t* wd = reinterpret_cast<uint32_t*>(&Wh[lrow * GH + lkh]);
            *reinterpret_cast<uint4*>(wd)     = make_uint4(u[0], u[1], u[2], u[3]);
            *reinterpret_cast<uint4*>(wd + 4) = make_uint4(u[4], u[5], u[6], u[7]);
        }
        // ---- stage A ----
        if (a_half) {
            const __half* arow = (const __half*)Av + (size_t)(m0 + lrow) * K + k0 + lkh;
            cp16s(asb + (uint32_t)((lrow * GH + lkh) * 2), arow);
            cp16s(asb + (uint32_t)((lrow * GH + lkh + 8) * 2), arow + 8);
            asm volatile("cp.async.commit_group;");
            asm volatile("cp.async.wait_group 0;");
        } else {
            const float* arow = (const float*)Av + (size_t)(m0 + lrow) * K + k0 + lkh;
            uint32_t u[8];
#pragma unroll
            for (int j = 0; j < 4; j++) {
                float4 v = *reinterpret_cast<const float4*>(arow + j * 4);
                u[2 * j]     = pack_h2(v.x, v.y);
                u[2 * j + 1] = pack_h2(v.z, v.w);
            }
            uint32_t* ad = reinterpret_cast<uint32_t*>(&Ah[lrow * GH + lkh]);
            *reinterpret_cast<uint4*>(ad)     = make_uint4(u[0], u[1], u[2], u[3]);
            *reinterpret_cast<uint4*>(ad + 4) = make_uint4(u[4], u[5], u[6], u[7]);
        }
        __syncthreads();

#pragma unroll
        for (int kk = 0; kk < 2; kk++) {
            const uint32_t kbb = (uint32_t)(kk * 32);   // 16 halves
            uint32_t a[2][4];
            ldsm4(a[0][0], a[0][1], a[0][2], a[0][3],
                  asb + (uint32_t)(wm * GH * 2) + lqA + kbb);
            ldsm4(a[1][0], a[1][1], a[1][2], a[1][3],
                  asb + (uint32_t)((wm + 16) * GH * 2) + lqA + kbb);
#pragma unroll
            for (int nb = 0; nb < 4; nb++) {
                uint32_t b00, b01, b10, b11;
                ldsm4(b00, b01, b10, b11,
                      wsb + (uint32_t)((wn + nb * 16) * GH * 2) + lkB + kbb);
                mma_f16(acc[0][2 * nb],     a[0][0], a[0][1], a[0][2], a[0][3], b00, b01);
                mma_f16(acc[1][2 * nb],     a[1][0], a[1][1], a[1][2], a[1][3], b00, b01);
                mma_f16(acc[0][2 * nb + 1], a[0][0], a[0][1], a[0][2], a[0][3], b10, b11);
                mma_f16(acc[1][2 * nb + 1], a[1][0], a[1][1], a[1][2], a[1][3], b10, b11);
            }
        }
        __syncthreads();
    }

#pragma unroll
    for (int mf = 0; mf < 2; mf++) {
        const int r0 = m0 + wm + mf * 16 + g;
#pragma unroll
        for (int nf = 0; nf < 8; nf++) {
            const int cc = n0 + wn + nf * 8 + 2 * tc;
            if (half_out) {
                __half* Ch = (__half*)Cv;
                *reinterpret_cast<uint32_t*>(&Ch[(size_t)r0 * N + cc]) =
                    pack_h2(acc[mf][nf][0], acc[mf][nf][1]);
                *reinterpret_cast<uint32_t*>(&Ch[(size_t)(r0 + 8) * N + cc]) =
                    pack_h2(acc[mf][nf][2], acc[mf][nf][3]);
            } else {
                float* Cf = (float*)Cv;
                *reinterpret_cast<float2*>(&Cf[(size_t)r0 * N + cc]) =
                    make_float2(acc[mf][nf][0], acc[mf][nf][1]);
                *reinterpret_cast<float2*>(&Cf[(size_t)(r0 + 8) * N + cc]) =
                    make_float2(acc[mf][nf][2], acc[mf][nf][3]);
            }
        }
    }
}

// ---------------------------------------------------------------------------
// Flash attention, fp16 m16n8k16 (fp32 accumulate). qkv is fp16: staged by
// bare cp.async (K/V double-buffered, one sync/tile). Q/K fragments via
// ldmatrix.x4; V via ldmatrix.x4.trans; P packs lane-locally. ctx out: fp16.
// ---------------------------------------------------------------------------
#define BR 128
#define BC 64
#define NT (LL / BC)
#define QPH 72                 // row stride in halves (144B, 16B aligned)
#define SB_K (BR * QPH * 2)    // 18432 B: Q tile
#define KSTB (BC * QPH * 2)    // 9216 B per K/V stage
#define SB_V (SB_K + 2 * KSTB)
#define ASM_BYTES (SB_V + 2 * KSTB)   // 55296 B -> 2 CTAs/SM

__global__ __launch_bounds__(256, 2) void attn_f16_kernel(
    const __half* __restrict__ qkv, __half* __restrict__ ctx)
{
    extern __shared__ uint32_t sm[];
    const uint32_t sb = smem_u32(sm);

    const int tid  = threadIdx.x;
    const int warp = tid >> 5;
    const int lane = tid & 31;
    const int g    = lane >> 2;
    const int tc   = lane & 3;
    const int wm   = warp * 16;

    const int bh = blockIdx.y;
    const int b  = bh >> 3;
    const int h  = bh & 7;
    const int q0 = blockIdx.x * BR;

    const __half* base = qkv + (size_t)b * LL * QKVN + h * DKK;

    const int lr  = tid >> 2;           // 0..63
    const int lc2 = (tid & 3) * 16;     // halves: 0,16,32,48

    const uint32_t lqQ = (uint32_t)(((wm + (lane & 15)) * QPH + (lane >> 4) * 8) * 2);
    const uint32_t lkK = (uint32_t)((((lane & 7) + (lane >> 4) * 8) * QPH
                                    + ((lane >> 3) & 1) * 8) * 2);
    const uint32_t lvV = (uint32_t)((((lane & 7) + ((lane >> 3) & 1) * 8) * QPH
                                    + (lane >> 4) * 8) * 2);

    // ---- Prologue: cp.async Q tile + K/V tile 0 ----
    {
        const int r   = tid >> 1;
        const int c0h = (tid & 1) * 32;
        const __half* qrow = base + (size_t)(q0 + r) * QKVN;
#pragma unroll
        for (int j = 0; j < 4; j++)
            cp16s(sb + (uint32_t)((r * QPH + c0h + 8 * j) * 2), qrow + c0h + 8 * j);

        const __half* krow = base + (size_t)lr * QKVN + DD;
        const __half* vrow = krow + DD;
#pragma unroll
        for (int j = 0; j < 2; j++) {
            cp16s(sb + SB_K + (uint32_t)((lr * QPH + lc2 + 8 * j) * 2), krow + lc2 + 8 * j);
            cp16s(sb + SB_V + (uint32_t)((lr * QPH + lc2 + 8 * j) * 2), vrow + lc2 + 8 * j);
        }
        asm volatile("cp.async.commit_group;");
        asm volatile("cp.async.wait_group 0;");
    }
    __syncthreads();

    float oa[8][4];
#pragma unroll
    for (int n = 0; n < 8; n++)
#pragma unroll
        for (int i = 0; i < 4; i++) oa[n][i] = 0.0f;
    float m0 = -1e30f, m1 = -1e30f;
    float l0 = 0.0f,  l1 = 0.0f;

    for (int t = 0; t < NT; t++) {
        const bool pf = (t + 1 < NT);
        const uint32_t ksb = sb + SB_K + (uint32_t)((t & 1) * KSTB);
        const uint32_t vsb = sb + SB_V + (uint32_t)((t & 1) * KSTB);

        if (pf) {
            const __half* krow = base + (size_t)((t + 1) * BC + lr) * QKVN + DD;
            const __half* vrow = krow + DD;
            const uint32_t kd = sb + SB_K + (uint32_t)(((t + 1) & 1) * KSTB);
            const uint32_t vd = sb + SB_V + (uint32_t)(((t + 1) & 1) * KSTB);
#pragma unroll
            for (int j = 0; j < 2; j++) {
                cp16s(kd + (uint32_t)((lr * QPH + lc2 + 8 * j) * 2), krow + lc2 + 8 * j);
                cp16s(vd + (uint32_t)((lr * QPH + lc2 + 8 * j) * 2), vrow + lc2 + 8 * j);
            }
            asm volatile("cp.async.commit_group;");
        }

        // S = Q @ K^T
        float sa[8][4];
#pragma unroll
        for (int n = 0; n < 8; n++)
#pragma unroll
            for (int i = 0; i < 4; i++) sa[n][i] = 0.0f;

#pragma unroll
        for (int kk = 0; kk < 4; kk++) {
            uint32_t a0, a1, a2, a3;
            ldsm4(a0, a1, a2, a3, sb + lqQ + (uint32_t)(kk * 32));
#pragma unroll
            for (int nb = 0; nb < 4; nb++) {
                uint32_t b00, b01, b10, b11;
                ldsm4(b00, b01, b10, b11,
                      ksb + lkK + (uint32_t)((nb * 16 * QPH + kk * 16) * 2));
                mma_f16(sa[2 * nb], a0, a1, a2, a3, b00, b01);
                mma_f16(sa[2 * nb + 1], a0, a1, a2, a3, b10, b11);
            }
        }

        // Online softmax (base-2, scale inside exp argument)
        float mx0 = -1e30f, mx1 = -1e30f;
#pragma unroll
        for (int n = 0; n < 8; n++) {
            mx0 = fmaxf(mx0, fmaxf(sa[n][0], sa[n][1]));
            mx1 = fmaxf(mx1, fmaxf(sa[n][2], sa[n][3]));
        }
        mx0 = fmaxf(mx0, __shfl_xor_sync(0xffffffffu, mx0, 1));
        mx0 = fmaxf(mx0, __shfl_xor_sync(0xffffffffu, mx0, 2));
        mx1 = fmaxf(mx1, __shfl_xor_sync(0xffffffffu, mx1, 1));
        mx1 = fmaxf(mx1, __shfl_xor_sync(0xffffffffu, mx1, 2));

        const bool upd = !__all_sync(0xffffffffu, (mx0 <= m0) & (mx1 <= m1));
        if (upd) {
            float mn0 = fmaxf(m0, mx0);
            float mn1 = fmaxf(m1, mx1);
            float alpha0 = ex2(CC * (m0 - mn0));
            float alpha1 = ex2(CC * (m1 - mn1));
            m0 = mn0; m1 = mn1;
            l0 *= alpha0;
            l1 *= alpha1;
#pragma unroll
            for (int n = 0; n < 8; n++) {
                oa[n][0] *= alpha0; oa[n][1] *= alpha0;
                oa[n][2] *= alpha1; oa[n][3] *= alpha1;
            }
        }

        const float nc0 = -CC * m0;
        const float nc1 = -CC * m1;
        float sum0 = 0.0f, sum1 = 0.0f;
#pragma unroll
        for (int n = 0; n < 8; n++) {
            float p0 = ex2(fmaf(CC, sa[n][0], nc0));
            float p1 = ex2(fmaf(CC, sa[n][1], nc0));
            float p2 = ex2(fmaf(CC, sa[n][2], nc1));
            float p3 = ex2(fmaf(CC, sa[n][3], nc1));
            sum0 += p0 + p1;
            sum1 += p2 + p3;
            sa[n][0] = p0; sa[n][1] = p1; sa[n][2] = p2; sa[n][3] = p3;
        }
        l0 += sum0;
        l1 += sum1;

        // O += P @ V
#pragma unroll
        for (int kk = 0; kk < 4; kk++) {
            uint32_t a0 = pack_h2(sa[2 * kk][0],     sa[2 * kk][1]);
            uint32_t a1 = pack_h2(sa[2 * kk][2],     sa[2 * kk][3]);
            uint32_t a2 = pack_h2(sa[2 * kk + 1][0], sa[2 * kk + 1][1]);
            uint32_t a3 = pack_h2(sa[2 * kk + 1][2], sa[2 * kk + 1][3]);
#pragma unroll
            for (int nb = 0; nb < 4; nb++) {
                uint32_t b00, b01, b10, b11;
                ldsm4t(b00, b01, b10, b11,
                       vsb + lvV + (uint32_t)((kk * 16 * QPH + nb * 16) * 2));
                mma_f16(oa[2 * nb], a0, a1, a2, a3, b00, b01);
                mma_f16(oa[2 * nb + 1], a0, a1, a2, a3, b10, b11);
            }
        }

        if (pf) { asm volatile("cp.async.wait_group 0;"); }
        __syncthreads();
    }

    // Finalize l, normalize, write ctx (fp16)
    l0 += __shfl_xor_sync(0xffffffffu, l0, 1);
    l0 += __shfl_xor_sync(0xffffffffu, l0, 2);
    l1 += __shfl_xor_sync(0xffffffffu, l1, 1);
    l1 += __shfl_xor_sync(0xffffffffu, l1, 2);
    float inv0 = 1.0f / l0;
    float inv1 = 1.0f / l1;

    const int r0 = q0 + wm + g;
    const int r1 = r0 + 8;
#pragma unroll
    for (int n = 0; n < 8; n++) {
        *reinterpret_cast<uint32_t*>(
            &ctx[(size_t)(b * LL + r0) * DD + h * DKK + n * 8 + 2 * tc]) =
            pack_h2(oa[n][0] * inv0, oa[n][1] * inv0);
        *reinterpret_cast<uint32_t*>(
            &ctx[(size_t)(b * LL + r1) * DD + h * DKK + n * 8 + 2 * tc]) =
            pack_h2(oa[n][2] * inv1, oa[n][3] * inv1);
    }
}

// ---------------------------------------------------------------------------
extern "C" void kernel_launch(void* const* d_in, const int* in_sizes, int n_in,
                              void* d_out, int out_size)
{
    const float* x     = (const float*)d_in[0];   // [B, L, D]
    const float* w_qkv = (const float*)d_in[1];   // [3D, D]
    const float* w_o   = (const float*)d_in[2];   // [D, D]
    float* out = (float*)d_out;                   // [B, L, D]

    __half* qkv_p = nullptr;
    __half* ctx_p = nullptr;
    cudaGetSymbolAddress((void**)&qkv_p, g_qkv);
    cudaGetSymbolAddress((void**)&ctx_p, g_ctx);
    cudaFuncSetAttribute(attn_f16_kernel, cudaFuncAttributeMaxDynamicSharedMemorySize, ASM_BYTES);

    // 1) qkv = x @ w_qkv^T : [8192, 1536], fp16 out
    {
        dim3 grid(QKVN / 128, MROWS / 128);
        gemm_f16_kernel<<<grid, 256>>>(x, w_qkv, qkv_p, MROWS, QKVN, DD, 0, 1);
    }
    // 2) attention -> ctx (fp16)
    {
        dim3 grid(LL / BR, BB * HH);
        attn_f16_kernel<<<grid, 256, ASM_BYTES>>>(qkv_p, ctx_p);
    }
    // 3) out = ctx @ w_o^T : [8192, 512], fp32 out, A staged as fp16
    {
        dim3 grid(DD / 128, MROWS / 128);
        gemm_f16_kernel<<<grid, 256>>>(ctx_p, w_o, out, MROWS, DD, DD, 1, 0);
    }
}

// round 12
// speedup vs baseline: 3.7279x; 1.0517x over previous
#include <cuda_runtime.h>
#include <cuda_fp16.h>
#include <math.h>
#include <stdint.h>

#define BB 2
#define LL 4096
#define DD 512
#define HH 8
#define DKK 64
#define MROWS (BB*LL)          // 8192
#define QKVN (3*DD)            // 1536
// softmax scale (1/sqrt(64) * log2(e)); applied inside exp2
#define CC (0.125f * 1.4426950408889634f)

// Scratch (allocation-free rule: __device__ globals)
__device__ __half g_x[(size_t)MROWS * DD];      // fp16 copy of x
__device__ __half g_wqkv[(size_t)QKVN * DD];    // fp16 copy of w_qkv
__device__ __half g_wo[(size_t)DD * DD];        // fp16 copy of w_o
__device__ __half g_qkv[(size_t)MROWS * QKVN];  // [B*L, 3*D] fp16
__device__ __half g_ctx[(size_t)MROWS * DD];    // [B*L, D]   fp16

// ---------------------------------------------------------------------------
// Helpers
// ---------------------------------------------------------------------------
__device__ __forceinline__ float ex2(float x) {
    float y;
    asm("ex2.approx.ftz.f32 %0, %1;" : "=f"(y) : "f"(x));
    return y;
}

__device__ __forceinline__ uint32_t pack_h2(float lo, float hi) {
    uint32_t r;
    asm("cvt.rn.f16x2.f32 %0, %1, %2;" : "=r"(r) : "f"(hi), "f"(lo));
    return r;
}

__device__ __forceinline__ void mma_f16(float c[4],
    uint32_t a0, uint32_t a1, uint32_t a2, uint32_t a3,
    uint32_t b0, uint32_t b1)
{
    asm volatile(
        "mma.sync.aligned.m16n8k16.row.col.f32.f16.f16.f32 "
        "{%0,%1,%2,%3}, {%4,%5,%6,%7}, {%8,%9}, {%0,%1,%2,%3};"
        : "+f"(c[0]), "+f"(c[1]), "+f"(c[2]), "+f"(c[3])
        : "r"(a0), "r"(a1), "r"(a2), "r"(a3), "r"(b0), "r"(b1));
}

__device__ __forceinline__ void ldsm4(uint32_t& r0, uint32_t& r1,
                                      uint32_t& r2, uint32_t& r3, uint32_t addr)
{
    asm volatile("ldmatrix.sync.aligned.m8n8.x4.shared.b16 {%0,%1,%2,%3}, [%4];"
                 : "=r"(r0), "=r"(r1), "=r"(r2), "=r"(r3) : "r"(addr));
}

__device__ __forceinline__ void ldsm4t(uint32_t& r0, uint32_t& r1,
                                       uint32_t& r2, uint32_t& r3, uint32_t addr)
{
    asm volatile("ldmatrix.sync.aligned.m8n8.x4.trans.shared.b16 {%0,%1,%2,%3}, [%4];"
                 : "=r"(r0), "=r"(r1), "=r"(r2), "=r"(r3) : "r"(addr));
}

__device__ __forceinline__ uint32_t smem_u32(const void* p) {
    uint32_t a;
    asm("{ .reg .u64 t; cvta.to.shared.u64 t, %1; cvt.u32.u64 %0, t; }"
        : "=r"(a) : "l"(p));
    return a;
}

__device__ __forceinline__ void cp16s(uint32_t smem_addr, const void* gptr) {
    asm volatile("cp.async.cg.shared.global [%0], [%1], 16;"
                 :: "r"(smem_addr), "l"(gptr));
}

// ---------------------------------------------------------------------------
// fp32 -> fp16 elementwise convert (n multiple of 8)
// ---------------------------------------------------------------------------
__global__ __launch_bounds__(256) void cvt_f16_kernel(
    const float* __restrict__ src, __half* __restrict__ dst, int n)
{
    int i = (blockIdx.x * 256 + threadIdx.x) * 8;
    if (i < n) {
        float4 v0 = *reinterpret_cast<const float4*>(src + i);
        float4 v1 = *reinterpret_cast<const float4*>(src + i + 4);
        uint4 u;
        u.x = pack_h2(v0.x, v0.y);
        u.y = pack_h2(v0.z, v0.w);
        u.z = pack_h2(v1.x, v1.y);
        u.w = pack_h2(v1.z, v1.w);
        *reinterpret_cast<uint4*>(dst + i) = u;
    }
}

// ---------------------------------------------------------------------------
// fp16 GEMM (m16n8k16, fp32 accum), 3-stage cp.async pipeline:
// C[M,N] = A[M,K] @ W[N,K]^T, both operands fp16 in gmem.
// 128x128 tiles, BK=32, 8 warps (4m x 2n), warp tile 32x64.
// Mainloop: zero LDG/STS/cvt; 4 cp.async per thread per iter; 1 sync/iter.
// ---------------------------------------------------------------------------
#define GH 40                      // halves per smem row (80 B stride)
#define STG_H (2 * 128 * GH)       // halves per stage (A block then W block)
#define D_ST 3
#define GSMB (D_ST * STG_H * 2)    // 61440 B

__global__ __launch_bounds__(256, 2) void gemm_f16_kernel(
    const __half* __restrict__ A, const __half* __restrict__ W,
    void* __restrict__ Cv, int M, int N, int K, int half_out)
{
    extern __shared__ __half gsm[];
    const uint32_t sb = smem_u32(gsm);

    const int tid  = threadIdx.x;
    const int warp = tid >> 5;
    const int lane = tid & 31;
    const int g    = lane >> 2;
    const int tc   = lane & 3;
    const int wm   = (warp >> 1) * 32;
    const int wn   = (warp & 1) * 64;
    const int m0   = blockIdx.y * 128;
    const int n0   = blockIdx.x * 128;

    // loader: threads 0-127 stage A rows, threads 128-255 stage W rows
    const bool isW = tid >= 128;
    const int lrow = tid & 127;
    const __half* grow = isW ? (W + (size_t)(n0 + lrow) * K)
                             : (A + (size_t)(m0 + lrow) * K);
    const uint32_t sof = (uint32_t)(((isW ? 128 * GH : 0) + lrow * GH) * 2);

    const uint32_t lqA = (uint32_t)(((lane & 15) * GH + (lane >> 4) * 8) * 2);
    const uint32_t lkB = (uint32_t)((((lane & 7) + (lane >> 4) * 8) * GH
                                    + ((lane >> 3) & 1) * 8) * 2);

    float acc[2][8][4];
#pragma unroll
    for (int mf = 0; mf < 2; mf++)
#pragma unroll
        for (int nf = 0; nf < 8; nf++)
#pragma unroll
            for (int i = 0; i < 4; i++) acc[mf][nf][i] = 0.0f;

    const int NK = K >> 5;   // BK=32 iters

    // Prologue: issue stages 0..D_ST-2
#pragma unroll
    for (int s = 0; s < D_ST - 1; s++) {
        if (s < NK) {
            const uint32_t st = sb + (uint32_t)(s * STG_H * 2) + sof;
            const __half* gp = grow + s * 32;
#pragma unroll
            for (int j = 0; j < 4; j++)
                cp16s(st + j * 16, gp + j * 8);
            asm volatile("cp.async.commit_group;");
        }
    }

    for (int i = 0; i < NK; i++) {
        if (i < NK - 1) { asm volatile("cp.async.wait_group 1;"); }
        else            { asm volatile("cp.async.wait_group 0;"); }
        __syncthreads();

        if (i + 2 < NK) {
            const int s = (i + 2) % D_ST;
            const uint32_t st = sb + (uint32_t)(s * STG_H * 2) + sof;
            const __half* gp = grow + (i + 2) * 32;
#pragma unroll
            for (int j = 0; j < 4; j++)
                cp16s(st + j * 16, gp + j * 8);
            asm volatile("cp.async.commit_group;");
        }

        const uint32_t asb = sb + (uint32_t)((i % D_ST) * STG_H * 2);
        const uint32_t wsb = asb + (uint32_t)(128 * GH * 2);
#pragma unroll
        for (int kk = 0; kk < 2; kk++) {
            const uint32_t kbb = (uint32_t)(kk * 32);   // 16 halves
            uint32_t a[2][4];
            ldsm4(a[0][0], a[0][1], a[0][2], a[0][3],
                  asb + (uint32_t)(wm * GH * 2) + lqA + kbb);
            ldsm4(a[1][0], a[1][1], a[1][2], a[1][3],
                  asb + (uint32_t)((wm + 16) * GH * 2) + lqA + kbb);
#pragma unroll
            for (int nb = 0; nb < 4; nb++) {
                uint32_t b00, b01, b10, b11;
                ldsm4(b00, b01, b10, b11,
                      wsb + (uint32_t)((wn + nb * 16) * GH * 2) + lkB + kbb);
                mma_f16(acc[0][2 * nb],     a[0][0], a[0][1], a[0][2], a[0][3], b00, b01);
                mma_f16(acc[1][2 * nb],     a[1][0], a[1][1], a[1][2], a[1][3], b00, b01);
                mma_f16(acc[0][2 * nb + 1], a[0][0], a[0][1], a[0][2], a[0][3], b10, b11);
                mma_f16(acc[1][2 * nb + 1], a[1][0], a[1][1], a[1][2], a[1][3], b10, b11);
            }
        }
    }

#pragma unroll
    for (int mf = 0; mf < 2; mf++) {
        const int r0 = m0 + wm + mf * 16 + g;
#pragma unroll
        for (int nf = 0; nf < 8; nf++) {
            const int cc = n0 + wn + nf * 8 + 2 * tc;
            if (half_out) {
                __half* Ch = (__half*)Cv;
                *reinterpret_cast<uint32_t*>(&Ch[(size_t)r0 * N + cc]) =
                    pack_h2(acc[mf][nf][0], acc[mf][nf][1]);
                *reinterpret_cast<uint32_t*>(&Ch[(size_t)(r0 + 8) * N + cc]) =
                    pack_h2(acc[mf][nf][2], acc[mf][nf][3]);
            } else {
                float* Cf = (float*)Cv;
                *reinterpret_cast<float2*>(&Cf[(size_t)r0 * N + cc]) =
                    make_float2(acc[mf][nf][0], acc[mf][nf][1]);
                *reinterpret_cast<float2*>(&Cf[(size_t)(r0 + 8) * N + cc]) =
                    make_float2(acc[mf][nf][2], acc[mf][nf][3]);
            }
        }
    }
}

// ---------------------------------------------------------------------------
// Flash attention, fp16 m16n8k16 (fp32 accumulate) — UNCHANGED from R11.
// ---------------------------------------------------------------------------
#define BR 128
#define BC 64
#define NT (LL / BC)
#define QPH 72
#define SB_K (BR * QPH * 2)
#define KSTB (BC * QPH * 2)
#define SB_V (SB_K + 2 * KSTB)
#define ASM_BYTES (SB_V + 2 * KSTB)   // 55296 B

__global__ __launch_bounds__(256, 2) void attn_f16_kernel(
    const __half* __restrict__ qkv, __half* __restrict__ ctx)
{
    extern __shared__ uint32_t sm[];
    const uint32_t sb = smem_u32(sm);

    const int tid  = threadIdx.x;
    const int warp = tid >> 5;
    const int lane = tid & 31;
    const int g    = lane >> 2;
    const int tc   = lane & 3;
    const int wm   = warp * 16;

    const int bh = blockIdx.y;
    const int b  = bh >> 3;
    const int h  = bh & 7;
    const int q0 = blockIdx.x * BR;

    const __half* base = qkv + (size_t)b * LL * QKVN + h * DKK;

    const int lr  = tid >> 2;
    const int lc2 = (tid & 3) * 16;

    const uint32_t lqQ = (uint32_t)(((wm + (lane & 15)) * QPH + (lane >> 4) * 8) * 2);
    const uint32_t lkK = (uint32_t)((((lane & 7) + (lane >> 4) * 8) * QPH
                                    + ((lane >> 3) & 1) * 8) * 2);
    const uint32_t lvV = (uint32_t)((((lane & 7) + ((lane >> 3) & 1) * 8) * QPH
                                    + (lane >> 4) * 8) * 2);

    {
        const int r   = tid >> 1;
        const int c0h = (tid & 1) * 32;
        const __half* qrow = base + (size_t)(q0 + r) * QKVN;
#pragma unroll
        for (int j = 0; j < 4; j++)
            cp16s(sb + (uint32_t)((r * QPH + c0h + 8 * j) * 2), qrow + c0h + 8 * j);

        const __half* krow = base + (size_t)lr * QKVN + DD;
        const __half* vrow = krow + DD;
#pragma unroll
        for (int j = 0; j < 2; j++) {
            cp16s(sb + SB_K + (uint32_t)((lr * QPH + lc2 + 8 * j) * 2), krow + lc2 + 8 * j);
            cp16s(sb + SB_V + (uint32_t)((lr * QPH + lc2 + 8 * j) * 2), vrow + lc2 + 8 * j);
        }
        asm volatile("cp.async.commit_group;");
        asm volatile("cp.async.wait_group 0;");
    }
    __syncthreads();

    float oa[8][4];
#pragma unroll
    for (int n = 0; n < 8; n++)
#pragma unroll
        for (int i = 0; i < 4; i++) oa[n][i] = 0.0f;
    float m0 = -1e30f, m1 = -1e30f;
    float l0 = 0.0f,  l1 = 0.0f;

    for (int t = 0; t < NT; t++) {
        const bool pf = (t + 1 < NT);
        const uint32_t ksb = sb + SB_K + (uint32_t)((t & 1) * KSTB);
        const uint32_t vsb = sb + SB_V + (uint32_t)((t & 1) * KSTB);

        if (pf) {
            const __half* krow = base + (size_t)((t + 1) * BC + lr) * QKVN + DD;
            const __half* vrow = krow + DD;
            const uint32_t kd = sb + SB_K + (uint32_t)(((t + 1) & 1) * KSTB);
            const uint32_t vd = sb + SB_V + (uint32_t)(((t + 1) & 1) * KSTB);
#pragma unroll
            for (int j = 0; j < 2; j++) {
                cp16s(kd + (uint32_t)((lr * QPH + lc2 + 8 * j) * 2), krow + lc2 + 8 * j);
                cp16s(vd + (uint32_t)((lr * QPH + lc2 + 8 * j) * 2), vrow + lc2 + 8 * j);
            }
            asm volatile("cp.async.commit_group;");
        }

        float sa[8][4];
#pragma unroll
        for (int n = 0; n < 8; n++)
#pragma unroll
            for (int i = 0; i < 4; i++) sa[n][i] = 0.0f;

#pragma unroll
        for (int kk = 0; kk < 4; kk++) {
            uint32_t a0, a1, a2, a3;
            ldsm4(a0, a1, a2, a3, sb + lqQ + (uint32_t)(kk * 32));
#pragma unroll
            for (int nb = 0; nb < 4; nb++) {
                uint32_t b00, b01, b10, b11;
                ldsm4(b00, b01, b10, b11,
                      ksb + lkK + (uint32_t)((nb * 16 * QPH + kk * 16) * 2));
                mma_f16(sa[2 * nb], a0, a1, a2, a3, b00, b01);
                mma_f16(sa[2 * nb + 1], a0, a1, a2, a3, b10, b11);
            }
        }

        float mx0 = -1e30f, mx1 = -1e30f;
#pragma unroll
        for (int n = 0; n < 8; n++) {
            mx0 = fmaxf(mx0, fmaxf(sa[n][0], sa[n][1]));
            mx1 = fmaxf(mx1, fmaxf(sa[n][2], sa[n][3]));
        }
        mx0 = fmaxf(mx0, __shfl_xor_sync(0xffffffffu, mx0, 1));
        mx0 = fmaxf(mx0, __shfl_xor_sync(0xffffffffu, mx0, 2));
        mx1 = fmaxf(mx1, __shfl_xor_sync(0xffffffffu, mx1, 1));
        mx1 = fmaxf(mx1, __shfl_xor_sync(0xffffffffu, mx1, 2));

        const bool upd = !__all_sync(0xffffffffu, (mx0 <= m0) & (mx1 <= m1));
        if (upd) {
            float mn0 = fmaxf(m0, mx0);
            float mn1 = fmaxf(m1, mx1);
            float alpha0 = ex2(CC * (m0 - mn0));
            float alpha1 = ex2(CC * (m1 - mn1));
            m0 = mn0; m1 = mn1;
            l0 *= alpha0;
            l1 *= alpha1;
#pragma unroll
            for (int n = 0; n < 8; n++) {
                oa[n][0] *= alpha0; oa[n][1] *= alpha0;
                oa[n][2] *= alpha1; oa[n][3] *= alpha1;
            }
        }

        const float nc0 = -CC * m0;
        const float nc1 = -CC * m1;
        float sum0 = 0.0f, sum1 = 0.0f;
#pragma unroll
        for (int n = 0; n < 8; n++) {
            float p0 = ex2(fmaf(CC, sa[n][0], nc0));
            float p1 = ex2(fmaf(CC, sa[n][1], nc0));
            float p2 = ex2(fmaf(CC, sa[n][2], nc1));
            float p3 = ex2(fmaf(CC, sa[n][3], nc1));
            sum0 += p0 + p1;
            sum1 += p2 + p3;
            sa[n][0] = p0; sa[n][1] = p1; sa[n][2] = p2; sa[n][3] = p3;
        }
        l0 += sum0;
        l1 += sum1;

#pragma unroll
        for (int kk = 0; kk < 4; kk++) {
            uint32_t a0 = pack_h2(sa[2 * kk][0],     sa[2 * kk][1]);
            uint32_t a1 = pack_h2(sa[2 * kk][2],     sa[2 * kk][3]);
            uint32_t a2 = pack_h2(sa[2 * kk + 1][0], sa[2 * kk + 1][1]);
            uint32_t a3 = pack_h2(sa[2 * kk + 1][2], sa[2 * kk + 1][3]);
#pragma unroll
            for (int nb = 0; nb < 4; nb++) {
                uint32_t b00, b01, b10, b11;
                ldsm4t(b00, b01, b10, b11,
                       vsb + lvV + (uint32_t)((kk * 16 * QPH + nb * 16) * 2));
                mma_f16(oa[2 * nb], a0, a1, a2, a3, b00, b01);
                mma_f16(oa[2 * nb + 1], a0, a1, a2, a3, b10, b11);
            }
        }

        if (pf) { asm volatile("cp.async.wait_group 0;"); }
        __syncthreads();
    }

    l0 += __shfl_xor_sync(0xffffffffu, l0, 1);
    l0 += __shfl_xor_sync(0xffffffffu, l0, 2);
    l1 += __shfl_xor_sync(0xffffffffu, l1, 1);
    l1 += __shfl_xor_sync(0xffffffffu, l1, 2);
    float inv0 = 1.0f / l0;
    float inv1 = 1.0f / l1;

    const int r0 = q0 + wm + g;
    const int r1 = r0 + 8;
#pragma unroll
    for (int n = 0; n < 8; n++) {
        *reinterpret_cast<uint32_t*>(
            &ctx[(size_t)(b * LL + r0) * DD + h * DKK + n * 8 + 2 * tc]) =
            pack_h2(oa[n][0] * inv0, oa[n][1] * inv0);
        *reinterpret_cast<uint32_t*>(
            &ctx[(size_t)(b * LL + r1) * DD + h * DKK + n * 8 + 2 * tc]) =
            pack_h2(oa[n][2] * inv1, oa[n][3] * inv1);
    }
}

// ---------------------------------------------------------------------------
extern "C" void kernel_launch(void* const* d_in, const int* in_sizes, int n_in,
                              void* d_out, int out_size)
{
    const float* x     = (const float*)d_in[0];   // [B, L, D]
    const float* w_qkv = (const float*)d_in[1];   // [3D, D]
    const float* w_o   = (const float*)d_in[2];   // [D, D]
    float* out = (float*)d_out;                   // [B, L, D]

    __half *x_p, *wqkv_p, *wo_p, *qkv_p, *ctx_p;
    cudaGetSymbolAddress((void**)&x_p,    g_x);
    cudaGetSymbolAddress((void**)&wqkv_p, g_wqkv);
    cudaGetSymbolAddress((void**)&wo_p,   g_wo);
    cudaGetSymbolAddress((void**)&qkv_p,  g_qkv);
    cudaGetSymbolAddress((void**)&ctx_p,  g_ctx);
    cudaFuncSetAttribute(gemm_f16_kernel, cudaFuncAttributeMaxDynamicSharedMemorySize, GSMB);
    cudaFuncSetAttribute(attn_f16_kernel, cudaFuncAttributeMaxDynamicSharedMemorySize, ASM_BYTES);

    // 0) fp32 -> fp16 conversions (one-time rounding, same as staging rounding)
    cvt_f16_kernel<<<(MROWS * DD) / 2048, 256>>>(x, x_p, MROWS * DD);
    cvt_f16_kernel<<<(QKVN * DD) / 2048, 256>>>(w_qkv, wqkv_p, QKVN * DD);
    cvt_f16_kernel<<<(DD * DD) / 2048, 256>>>(w_o, wo_p, DD * DD);

    // 1) qkv = x @ w_qkv^T : [8192, 1536], fp16 out
    {
        dim3 grid(QKVN / 128, MROWS / 128);
        gemm_f16_kernel<<<grid, 256, GSMB>>>(x_p, wqkv_p, qkv_p, MROWS, QKVN, DD, 1);
    }
    // 2) attention -> ctx (fp16)
    {
        dim3 grid(LL / BR, BB * HH);
        attn_f16_kernel<<<grid, 256, ASM_BYTES>>>(qkv_p, ctx_p);
    }
    // 3) out = ctx @ w_o^T : [8192, 512], fp32 out
    {
        dim3 grid(DD / 128, MROWS / 128);
        gemm_f16_kernel<<<grid, 256, GSMB>>>(ctx_p, wo_p, out, MROWS, DD, DD, 0);
    }
}

// round 13
// speedup vs baseline: 3.7670x; 1.0105x over previous
#include <cuda_runtime.h>
#include <cuda_fp16.h>
#include <math.h>
#include <stdint.h>

#define BB 2
#define LL 4096
#define DD 512
#define HH 8
#define DKK 64
#define MROWS (BB*LL)          // 8192
#define QKVN (3*DD)            // 1536
// softmax scale (1/sqrt(64) * log2(e)); applied inside exp2
#define CC (0.125f * 1.4426950408889634f)

// Scratch (allocation-free rule: __device__ globals)
__device__ __half g_x[(size_t)MROWS * DD];      // fp16 copy of x
__device__ __half g_wqkv[(size_t)QKVN * DD];    // fp16 copy of w_qkv
__device__ __half g_wo[(size_t)DD * DD];        // fp16 copy of w_o
__device__ __half g_qkv[(size_t)MROWS * QKVN];  // [B*L, 3*D] fp16
__device__ __half g_ctx[(size_t)MROWS * DD];    // [B*L, D]   fp16

// ---------------------------------------------------------------------------
// Helpers
// ---------------------------------------------------------------------------
__device__ __forceinline__ float ex2(float x) {
    float y;
    asm("ex2.approx.ftz.f32 %0, %1;" : "=f"(y) : "f"(x));
    return y;
}

__device__ __forceinline__ uint32_t pack_h2(float lo, float hi) {
    uint32_t r;
    asm("cvt.rn.f16x2.f32 %0, %1, %2;" : "=r"(r) : "f"(hi), "f"(lo));
    return r;
}

__device__ __forceinline__ void mma_f16(float c[4],
    uint32_t a0, uint32_t a1, uint32_t a2, uint32_t a3,
    uint32_t b0, uint32_t b1)
{
    asm volatile(
        "mma.sync.aligned.m16n8k16.row.col.f32.f16.f16.f32 "
        "{%0,%1,%2,%3}, {%4,%5,%6,%7}, {%8,%9}, {%0,%1,%2,%3};"
        : "+f"(c[0]), "+f"(c[1]), "+f"(c[2]), "+f"(c[3])
        : "r"(a0), "r"(a1), "r"(a2), "r"(a3), "r"(b0), "r"(b1));
}

__device__ __forceinline__ void ldsm4(uint32_t& r0, uint32_t& r1,
                                      uint32_t& r2, uint32_t& r3, uint32_t addr)
{
    asm volatile("ldmatrix.sync.aligned.m8n8.x4.shared.b16 {%0,%1,%2,%3}, [%4];"
                 : "=r"(r0), "=r"(r1), "=r"(r2), "=r"(r3) : "r"(addr));
}

__device__ __forceinline__ void ldsm4t(uint32_t& r0, uint32_t& r1,
                                       uint32_t& r2, uint32_t& r3, uint32_t addr)
{
    asm volatile("ldmatrix.sync.aligned.m8n8.x4.trans.shared.b16 {%0,%1,%2,%3}, [%4];"
                 : "=r"(r0), "=r"(r1), "=r"(r2), "=r"(r3) : "r"(addr));
}

__device__ __forceinline__ uint32_t smem_u32(const void* p) {
    uint32_t a;
    asm("{ .reg .u64 t; cvta.to.shared.u64 t, %1; cvt.u32.u64 %0, t; }"
        : "=r"(a) : "l"(p));
    return a;
}

__device__ __forceinline__ void cp16s(uint32_t smem_addr, const void* gptr) {
    asm volatile("cp.async.cg.shared.global [%0], [%1], 16;"
                 :: "r"(smem_addr), "l"(gptr));
}

// ---------------------------------------------------------------------------
// Merged fp32->fp16 convert for x, w_qkv, w_o in ONE launch.
// ---------------------------------------------------------------------------
#define N1 (MROWS * DD)        // 4194304
#define N2 (QKVN * DD)         // 786432
#define N3 (DD * DD)           // 262144
#define NTOT (N1 + N2 + N3)    // 5242880

__global__ __launch_bounds__(256) void cvt_all_kernel(
    const float* __restrict__ x, const float* __restrict__ wqkv,
    const float* __restrict__ wo,
    __half* __restrict__ dx, __half* __restrict__ dwqkv, __half* __restrict__ dwo)
{
    int i = (blockIdx.x * 256 + threadIdx.x) * 8;
    if (i >= NTOT) return;
    const float* src;
    __half* dst;
    if (i < N1)           { src = x + i;              dst = dx + i; }
    else if (i < N1 + N2) { src = wqkv + (i - N1);    dst = dwqkv + (i - N1); }
    else                  { src = wo + (i - N1 - N2); dst = dwo + (i - N1 - N2); }
    float4 v0 = *reinterpret_cast<const float4*>(src);
    float4 v1 = *reinterpret_cast<const float4*>(src + 4);
    uint4 u;
    u.x = pack_h2(v0.x, v0.y);
    u.y = pack_h2(v0.z, v0.w);
    u.z = pack_h2(v1.x, v1.y);
    u.w = pack_h2(v1.z, v1.w);
    *reinterpret_cast<uint4*>(dst) = u;
}

// ---------------------------------------------------------------------------
// fp16 GEMM (m16n8k16, fp32 accum), 3-stage cp.async pipeline — UNCHANGED
// from R12 (near its HMMA floor).
// ---------------------------------------------------------------------------
#define GH 40
#define STG_H (2 * 128 * GH)
#define D_ST 3
#define GSMB (D_ST * STG_H * 2)    // 61440 B

__global__ __launch_bounds__(256, 2) void gemm_f16_kernel(
    const __half* __restrict__ A, const __half* __restrict__ W,
    void* __restrict__ Cv, int M, int N, int K, int half_out)
{
    extern __shared__ __half gsm[];
    const uint32_t sb = smem_u32(gsm);

    const int tid  = threadIdx.x;
    const int warp = tid >> 5;
    const int lane = tid & 31;
    const int g    = lane >> 2;
    const int tc   = lane & 3;
    const int wm   = (warp >> 1) * 32;
    const int wn   = (warp & 1) * 64;
    const int m0   = blockIdx.y * 128;
    const int n0   = blockIdx.x * 128;

    const bool isW = tid >= 128;
    const int lrow = tid & 127;
    const __half* grow = isW ? (W + (size_t)(n0 + lrow) * K)
                             : (A + (size_t)(m0 + lrow) * K);
    const uint32_t sof = (uint32_t)(((isW ? 128 * GH : 0) + lrow * GH) * 2);

    const uint32_t lqA = (uint32_t)(((lane & 15) * GH + (lane >> 4) * 8) * 2);
    const uint32_t lkB = (uint32_t)((((lane & 7) + (lane >> 4) * 8) * GH
                                    + ((lane >> 3) & 1) * 8) * 2);

    float acc[2][8][4];
#pragma unroll
    for (int mf = 0; mf < 2; mf++)
#pragma unroll
        for (int nf = 0; nf < 8; nf++)
#pragma unroll
            for (int i = 0; i < 4; i++) acc[mf][nf][i] = 0.0f;

    const int NK = K >> 5;

#pragma unroll
    for (int s = 0; s < D_ST - 1; s++) {
        if (s < NK) {
            const uint32_t st = sb + (uint32_t)(s * STG_H * 2) + sof;
            const __half* gp = grow + s * 32;
#pragma unroll
            for (int j = 0; j < 4; j++)
                cp16s(st + j * 16, gp + j * 8);
            asm volatile("cp.async.commit_group;");
        }
    }

    for (int i = 0; i < NK; i++) {
        if (i < NK - 1) { asm volatile("cp.async.wait_group 1;"); }
        else            { asm volatile("cp.async.wait_group 0;"); }
        __syncthreads();

        if (i + 2 < NK) {
            const int s = (i + 2) % D_ST;
            const uint32_t st = sb + (uint32_t)(s * STG_H * 2) + sof;
            const __half* gp = grow + (i + 2) * 32;
#pragma unroll
            for (int j = 0; j < 4; j++)
                cp16s(st + j * 16, gp + j * 8);
            asm volatile("cp.async.commit_group;");
        }

        const uint32_t asb = sb + (uint32_t)((i % D_ST) * STG_H * 2);
        const uint32_t wsb = asb + (uint32_t)(128 * GH * 2);
#pragma unroll
        for (int kk = 0; kk < 2; kk++) {
            const uint32_t kbb = (uint32_t)(kk * 32);
            uint32_t a[2][4];
            ldsm4(a[0][0], a[0][1], a[0][2], a[0][3],
                  asb + (uint32_t)(wm * GH * 2) + lqA + kbb);
            ldsm4(a[1][0], a[1][1], a[1][2], a[1][3],
                  asb + (uint32_t)((wm + 16) * GH * 2) + lqA + kbb);
#pragma unroll
            for (int nb = 0; nb < 4; nb++) {
                uint32_t b00, b01, b10, b11;
                ldsm4(b00, b01, b10, b11,
                      wsb + (uint32_t)((wn + nb * 16) * GH * 2) + lkB + kbb);
                mma_f16(acc[0][2 * nb],     a[0][0], a[0][1], a[0][2], a[0][3], b00, b01);
                mma_f16(acc[1][2 * nb],     a[1][0], a[1][1], a[1][2], a[1][3], b00, b01);
                mma_f16(acc[0][2 * nb + 1], a[0][0], a[0][1], a[0][2], a[0][3], b10, b11);
                mma_f16(acc[1][2 * nb + 1], a[1][0], a[1][1], a[1][2], a[1][3], b10, b11);
            }
        }
    }

#pragma unroll
    for (int mf = 0; mf < 2; mf++) {
        const int r0 = m0 + wm + mf * 16 + g;
#pragma unroll
        for (int nf = 0; nf < 8; nf++) {
            const int cc = n0 + wn + nf * 8 + 2 * tc;
            if (half_out) {
                __half* Ch = (__half*)Cv;
                *reinterpret_cast<uint32_t*>(&Ch[(size_t)r0 * N + cc]) =
                    pack_h2(acc[mf][nf][0], acc[mf][nf][1]);
                *reinterpret_cast<uint32_t*>(&Ch[(size_t)(r0 + 8) * N + cc]) =
                    pack_h2(acc[mf][nf][2], acc[mf][nf][3]);
            } else {
                float* Cf = (float*)Cv;
                *reinterpret_cast<float2*>(&Cf[(size_t)r0 * N + cc]) =
                    make_float2(acc[mf][nf][0], acc[mf][nf][1]);
                *reinterpret_cast<float2*>(&Cf[(size_t)(r0 + 8) * N + cc]) =
                    make_float2(acc[mf][nf][2], acc[mf][nf][3]);
            }
        }
    }
}

// ---------------------------------------------------------------------------
// Flash attention, fp16 m16n8k16. 4-stage K/V ring, TWO tiles per barrier
// (32 barriers instead of 64). Fragments via ldmatrix / ldmatrix.trans.
// ---------------------------------------------------------------------------
#define BR 128
#define BC 64
#define NT (LL / BC)
#define QPH 72
#define QB   (BR * QPH * 2)        // 18432 B  Q tile
#define KSTB (BC * QPH * 2)        // 9216 B per K/V stage
#define SB_K QB
#define SB_V (QB + 4 * KSTB)
#define ASM_BYTES (QB + 8 * KSTB)  // 92160 B -> 2 CTAs/SM

__global__ __launch_bounds__(256, 2) void attn_f16_kernel(
    const __half* __restrict__ qkv, __half* __restrict__ ctx)
{
    extern __shared__ uint32_t sm[];
    const uint32_t sb = smem_u32(sm);

    const int tid  = threadIdx.x;
    const int warp = tid >> 5;
    const int lane = tid & 31;
    const int g    = lane >> 2;
    const int tc   = lane & 3;
    const int wm   = warp * 16;

    const int bh = blockIdx.y;
    const int b  = bh >> 3;
    const int h  = bh & 7;
    const int q0 = blockIdx.x * BR;

    const __half* base = qkv + (size_t)b * LL * QKVN + h * DKK;

    const int lr  = tid >> 2;
    const int lc2 = (tid & 3) * 16;

    const uint32_t lqQ = (uint32_t)(((wm + (lane & 15)) * QPH + (lane >> 4) * 8) * 2);
    const uint32_t lkK = (uint32_t)((((lane & 7) + (lane >> 4) * 8) * QPH
                                    + ((lane >> 3) & 1) * 8) * 2);
    const uint32_t lvV = (uint32_t)((((lane & 7) + ((lane >> 3) & 1) * 8) * QPH
                                    + (lane >> 4) * 8) * 2);

    // ---- Prologue: Q + K/V tiles 0 and 1 ----
    {
        const int r   = tid >> 1;
        const int c0h = (tid & 1) * 32;
        const __half* qrow = base + (size_t)(q0 + r) * QKVN;
#pragma unroll
        for (int j = 0; j < 4; j++)
            cp16s(sb + (uint32_t)((r * QPH + c0h + 8 * j) * 2), qrow + c0h + 8 * j);

#pragma unroll
        for (int u = 0; u < 2; u++) {
            const __half* krow = base + (size_t)(u * BC + lr) * QKVN + DD;
            const __half* vrow = krow + DD;
            const uint32_t kd = sb + SB_K + (uint32_t)(u * KSTB);
            const uint32_t vd = sb + SB_V + (uint32_t)(u * KSTB);
#pragma unroll
            for (int j = 0; j < 2; j++) {
                cp16s(kd + (uint32_t)((lr * QPH + lc2 + 8 * j) * 2), krow + lc2 + 8 * j);
                cp16s(vd + (uint32_t)((lr * QPH + lc2 + 8 * j) * 2), vrow + lc2 + 8 * j);
            }
        }
        asm volatile("cp.async.commit_group;");
        asm volatile("cp.async.wait_group 0;");
    }
    __syncthreads();

    float oa[8][4];
#pragma unroll
    for (int n = 0; n < 8; n++)
#pragma unroll
        for (int i = 0; i < 4; i++) oa[n][i] = 0.0f;
    float m0 = -1e30f, m1 = -1e30f;
    float l0 = 0.0f,  l1 = 0.0f;

    for (int t = 0; t < NT; t += 2) {
        // Prefetch tiles t+2, t+3 into ring stages (one commit group).
        if (t + 2 < NT) {
#pragma unroll
            for (int u = 0; u < 2; u++) {
                const int tt = t + 2 + u;
                const __half* krow = base + (size_t)(tt * BC + lr) * QKVN + DD;
                const __half* vrow = krow + DD;
                const uint32_t kd = sb + SB_K + (uint32_t)((tt & 3) * KSTB);
                const uint32_t vd = sb + SB_V + (uint32_t)((tt & 3) * KSTB);
#pragma unroll
                for (int j = 0; j < 2; j++) {
                    cp16s(kd + (uint32_t)((lr * QPH + lc2 + 8 * j) * 2), krow + lc2 + 8 * j);
                    cp16s(vd + (uint32_t)((lr * QPH + lc2 + 8 * j) * 2), vrow + lc2 + 8 * j);
                }
            }
            asm volatile("cp.async.commit_group;");
        }

        // Process tiles t and t+1.
#pragma unroll
        for (int u = 0; u < 2; u++) {
            const int tt = t + u;
            const uint32_t ksb = sb + SB_K + (uint32_t)((tt & 3) * KSTB);
            const uint32_t vsb = sb + SB_V + (uint32_t)((tt & 3) * KSTB);

            float sa[8][4];
#pragma unroll
            for (int n = 0; n < 8; n++)
#pragma unroll
                for (int i = 0; i < 4; i++) sa[n][i] = 0.0f;

#pragma unroll
            for (int kk = 0; kk < 4; kk++) {
                uint32_t a0, a1, a2, a3;
                ldsm4(a0, a1, a2, a3, sb + lqQ + (uint32_t)(kk * 32));
#pragma unroll
                for (int nb = 0; nb < 4; nb++) {
                    uint32_t b00, b01, b10, b11;
                    ldsm4(b00, b01, b10, b11,
                          ksb + lkK + (uint32_t)((nb * 16 * QPH + kk * 16) * 2));
                    mma_f16(sa[2 * nb], a0, a1, a2, a3, b00, b01);
                    mma_f16(sa[2 * nb + 1], a0, a1, a2, a3, b10, b11);
                }
            }

            float mx0 = -1e30f, mx1 = -1e30f;
#pragma unroll
            for (int n = 0; n < 8; n++) {
                mx0 = fmaxf(mx0, fmaxf(sa[n][0], sa[n][1]));
                mx1 = fmaxf(mx1, fmaxf(sa[n][2], sa[n][3]));
            }
            mx0 = fmaxf(mx0, __shfl_xor_sync(0xffffffffu, mx0, 1));
            mx0 = fmaxf(mx0, __shfl_xor_sync(0xffffffffu, mx0, 2));
            mx1 = fmaxf(mx1, __shfl_xor_sync(0xffffffffu, mx1, 1));
            mx1 = fmaxf(mx1, __shfl_xor_sync(0xffffffffu, mx1, 2));

            const bool upd = !__all_sync(0xffffffffu, (mx0 <= m0) & (mx1 <= m1));
            if (upd) {
                float mn0 = fmaxf(m0, mx0);
                float mn1 = fmaxf(m1, mx1);
                float alpha0 = ex2(CC * (m0 - mn0));
                float alpha1 = ex2(CC * (m1 - mn1));
                m0 = mn0; m1 = mn1;
                l0 *= alpha0;
                l1 *= alpha1;
#pragma unroll
                for (int n = 0; n < 8; n++) {
                    oa[n][0] *= alpha0; oa[n][1] *= alpha0;
                    oa[n][2] *= alpha1; oa[n][3] *= alpha1;
                }
            }

            const float nc0 = -CC * m0;
            const float nc1 = -CC * m1;
            float sum0 = 0.0f, sum1 = 0.0f;
#pragma unroll
            for (int n = 0; n < 8; n++) {
                float p0 = ex2(fmaf(CC, sa[n][0], nc0));
                float p1 = ex2(fmaf(CC, sa[n][1], nc0));
                float p2 = ex2(fmaf(CC, sa[n][2], nc1));
                float p3 = ex2(fmaf(CC, sa[n][3], nc1));
                sum0 += p0 + p1;
                sum1 += p2 + p3;
                sa[n][0] = p0; sa[n][1] = p1; sa[n][2] = p2; sa[n][3] = p3;
            }
            l0 += sum0;
            l1 += sum1;

#pragma unroll
            for (int kk = 0; kk < 4; kk++) {
                uint32_t a0 = pack_h2(sa[2 * kk][0],     sa[2 * kk][1]);
                uint32_t a1 = pack_h2(sa[2 * kk][2],     sa[2 * kk][3]);
                uint32_t a2 = pack_h2(sa[2 * kk + 1][0], sa[2 * kk + 1][1]);
                uint32_t a3 = pack_h2(sa[2 * kk + 1][2], sa[2 * kk + 1][3]);
#pragma unroll
                for (int nb = 0; nb < 4; nb++) {
                    uint32_t b00, b01, b10, b11;
                    ldsm4t(b00, b01, b10, b11,
                           vsb + lvV + (uint32_t)((kk * 16 * QPH + nb * 16) * 2));
                    mma_f16(oa[2 * nb], a0, a1, a2, a3, b00, b01);
                    mma_f16(oa[2 * nb + 1], a0, a1, a2, a3, b10, b11);
                }
            }
        }

        asm volatile("cp.async.wait_group 0;");
        __syncthreads();
    }

    l0 += __shfl_xor_sync(0xffffffffu, l0, 1);
    l0 += __shfl_xor_sync(0xffffffffu, l0, 2);
    l1 += __shfl_xor_sync(0xffffffffu, l1, 1);
    l1 += __shfl_xor_sync(0xffffffffu, l1, 2);
    float inv0 = 1.0f / l0;
    float inv1 = 1.0f / l1;

    const int r0 = q0 + wm + g;
    const int r1 = r0 + 8;
#pragma unroll
    for (int n = 0; n < 8; n++) {
        *reinterpret_cast<uint32_t*>(
            &ctx[(size_t)(b * LL + r0) * DD + h * DKK + n * 8 + 2 * tc]) =
            pack_h2(oa[n][0] * inv0, oa[n][1] * inv0);
        *reinterpret_cast<uint32_t*>(
            &ctx[(size_t)(b * LL + r1) * DD + h * DKK + n * 8 + 2 * tc]) =
            pack_h2(oa[n][2] * inv1, oa[n][3] * inv1);
    }
}

// ---------------------------------------------------------------------------
extern "C" void kernel_launch(void* const* d_in, const int* in_sizes, int n_in,
                              void* d_out, int out_size)
{
    const float* x     = (const float*)d_in[0];   // [B, L, D]
    const float* w_qkv = (const float*)d_in[1];   // [3D, D]
    const float* w_o   = (const float*)d_in[2];   // [D, D]
    float* out = (float*)d_out;                   // [B, L, D]

    __half *x_p, *wqkv_p, *wo_p, *qkv_p, *ctx_p;
    cudaGetSymbolAddress((void**)&x_p,    g_x);
    cudaGetSymbolAddress((void**)&wqkv_p, g_wqkv);
    cudaGetSymbolAddress((void**)&wo_p,   g_wo);
    cudaGetSymbolAddress((void**)&qkv_p,  g_qkv);
    cudaGetSymbolAddress((void**)&ctx_p,  g_ctx);
    cudaFuncSetAttribute(gemm_f16_kernel, cudaFuncAttributeMaxDynamicSharedMemorySize, GSMB);
    cudaFuncSetAttribute(attn_f16_kernel, cudaFuncAttributeMaxDynamicSharedMemorySize, ASM_BYTES);

    // 0) fp32 -> fp16 conversion, single launch for all three tensors
    cvt_all_kernel<<<(NTOT / 8 + 255) / 256, 256>>>(x, w_qkv, w_o, x_p, wqkv_p, wo_p);

    // 1) qkv = x @ w_qkv^T : [8192, 1536], fp16 out
    {
        dim3 grid(QKVN / 128, MROWS / 128);
        gemm_f16_kernel<<<grid, 256, GSMB>>>(x_p, wqkv_p, qkv_p, MROWS, QKVN, DD, 1);
    }
    // 2) attention -> ctx (fp16)
    {
        dim3 grid(LL / BR, BB * HH);
        attn_f16_kernel<<<grid, 256, ASM_BYTES>>>(qkv_p, ctx_p);
    }
    // 3) out = ctx @ w_o^T : [8192, 512], fp32 out
    {
        dim3 grid(DD / 128, MROWS / 128);
        gemm_f16_kernel<<<grid, 256, GSMB>>>(ctx_p, wo_p, out, MROWS, DD, DD, 0);
    }
}